// round 9
// baseline (speedup 1.0000x reference)
#include <cuda_runtime.h>
#include <cuda_bf16.h>
#include <cstdint>

#define BB 4096
#define MAXN 12
#define HID 301
#define NT 10
#define PP 9
#define VSTAT 310
#define KP 320          // padded hidden
#define KS 960          // K concat: act [hi|lo|hi], weights [hi|hi|lo]
#define JT 32           // j-cols per block
#define MB 64           // batch rows per block
#define KC 32           // K per chunk
#define NCH 30          // 960/32
#define SROW 40         // smem row stride in halves (80B; ldsm conflict-free)

#define A_HALVES (MB * SROW)            // 2560
#define BGRU_ROWS 96
#define BGT_ROWS 64
#define STG_GRU ((MB + BGRU_ROWS) * SROW * 2)   // 12800 B
#define STG_GT  ((MB + BGT_ROWS) * SROW * 2)    // 10240 B
#define GRU_SMEM (4 * STG_GRU)                  // 51200
#define GT_SMEM  (4 * STG_GT + MB * MAXN * 4)   // 44032

// ---------------- scratch (device globals; zero-initialized) ----------------
__device__ __align__(16) float d_g[(size_t)BB * 11 * KP];
__device__ __align__(16) float d_hcur[(size_t)BB * KP];
__device__ __align__(16) float d_hin[(size_t)BB * KP];
__device__ __align__(16) __nv_bfloat16 d_hAS[(size_t)BB * KS];
__device__ __align__(16) __nv_bfloat16 d_iAS[(size_t)BB * KS];
__device__ __align__(16) __nv_bfloat16 d_WhhS[960 * KS];   // rows s*320+j
__device__ __align__(16) __nv_bfloat16 d_WgmS[640 * KS];   // rows m*320+j

__device__ __forceinline__ float sigm(float x) { return 1.f / (1.f + __expf(-x)); }
__device__ __forceinline__ void bsplit(float x, __nv_bfloat16& hi, __nv_bfloat16& lo) {
    hi = __float2bfloat16_rn(x);
    lo = __float2bfloat16_rn(x - __bfloat162float(hi));
}
__device__ __forceinline__ void mma_bf16(float c[4], const uint32_t a[4],
                                         uint32_t b0, uint32_t b1) {
    asm volatile(
        "mma.sync.aligned.m16n8k16.row.col.f32.bf16.bf16.f32 "
        "{%0,%1,%2,%3}, {%4,%5,%6,%7}, {%8,%9}, {%0,%1,%2,%3};"
        : "+f"(c[0]), "+f"(c[1]), "+f"(c[2]), "+f"(c[3])
        : "r"(a[0]), "r"(a[1]), "r"(a[2]), "r"(a[3]), "r"(b0), "r"(b1));
}
__device__ __forceinline__ void ldsm4(uint32_t* r, uint32_t addr) {
    asm volatile("ldmatrix.sync.aligned.m8n8.x4.shared.b16 {%0,%1,%2,%3}, [%4];"
                 : "=r"(r[0]), "=r"(r[1]), "=r"(r[2]), "=r"(r[3]) : "r"(addr));
}
__device__ __forceinline__ void cpa16(uint32_t s, const void* g) {
    asm volatile("cp.async.ca.shared.global [%0], [%1], 16;" :: "r"(s), "l"(g));
}
#define CP_COMMIT() asm volatile("cp.async.commit_group;")
template<int N> __device__ __forceinline__ void cp_wait() {
    asm volatile("cp.async.wait_group %0;" :: "n"(N));
}

// ---------------- weight repack + bf16 split (pads stay zero) ---------------
__global__ void k_pad(const float* __restrict__ Whh, const float* __restrict__ Wg,
                      const float* __restrict__ Wm)
{
    int idx = blockIdx.x * blockDim.x + threadIdx.x;
    const int total = HID * HID;
    if (idx < 3 * total) {
        int s = idx / total, r = idx - s * total, j = r / HID, k = r - j * HID;
        __nv_bfloat16 hi, lo;
        bsplit(Whh[(s * HID + j) * HID + k], hi, lo);
        size_t row = (size_t)(s * KP + j) * KS;
        d_WhhS[row + k] = hi; d_WhhS[row + KP + k] = hi; d_WhhS[row + 2 * KP + k] = lo;
    } else if (idx < 5 * total) {
        int m = (idx - 3 * total) / total, r = (idx - 3 * total) % total;
        int j = r / HID, k = r - j * HID;
        const float* W = m ? Wm : Wg;
        __nv_bfloat16 hi, lo;
        bsplit(W[j * VSTAT + k], hi, lo);
        size_t row = (size_t)(m * KP + j) * KS;
        d_WgmS[row + k] = hi; d_WgmS[row + KP + k] = hi; d_WgmS[row + 2 * KP + k] = lo;
    }
}

// ---------------- node 0: h0 = gru(x0, 0) -----------------------------------
__global__ void k_h0(const int* __restrict__ types, const int* __restrict__ paths,
                     const float* __restrict__ W_ih, const float* __restrict__ b_ih,
                     const float* __restrict__ b_hh)
{
    int idx = blockIdx.x * blockDim.x + threadIdx.x;
    if (idx >= BB * HID) return;
    int b = idx / HID, j = idx - b * HID;
    int t = types[b * MAXN], p = paths[b * MAXN];
    float ir  = W_ih[j * 19 + t]            + W_ih[j * 19 + NT + p]            + b_ih[j];
    float iz  = W_ih[(j + HID) * 19 + t]    + W_ih[(j + HID) * 19 + NT + p]    + b_ih[j + HID];
    float inn = W_ih[(j + 2*HID) * 19 + t]  + W_ih[(j + 2*HID) * 19 + NT + p]  + b_ih[j + 2*HID];
    float r = sigm(ir + b_hh[j]);
    float z = sigm(iz + b_hh[j + HID]);
    float n = tanhf(inn + r * b_hh[j + 2*HID]);
    float h = (1.f - z) * n;
    d_hcur[(size_t)b * KP + j] = h;
    __nv_bfloat16 hi, lo; bsplit(h, hi, lo);
    size_t o = (size_t)b * KS + j;
    d_hAS[o] = hi; d_hAS[o + KP] = lo; d_hAS[o + 2 * KP] = hi;
}

// ============================================================================
// Fused GRU GEMM+epilogue. 64 batch x 32 j x 3 gates, K=960 bf16.
// 4-stage cp.async (KC=32), ldmatrix, occupancy 4. Epilogue via smem.
// ============================================================================
__global__ void __launch_bounds__(256, 4) k_ggru(int v,
    const int* __restrict__ types, const int* __restrict__ paths,
    const float* __restrict__ W_ih,
    const float* __restrict__ b_ih, const float* __restrict__ b_hh)
{
    extern __shared__ __nv_bfloat16 sm[];
    int tid = threadIdx.x, lane = tid & 31, wid = tid >> 5;
    int li = lane >> 3, lt = lane & 7;
    int wm = wid >> 1, wn = wid & 1;       // 4(M) x 2(N)
    int b0 = blockIdx.x * MB, j0 = blockIdx.y * JT;

    float c[6][4];
#pragma unroll
    for (int nf = 0; nf < 6; ++nf)
#pragma unroll
        for (int i = 0; i < 4; ++i) c[nf][i] = 0.f;

    uint32_t sbase = (uint32_t)__cvta_generic_to_shared(sm);

    // ldmatrix per-lane byte offsets within a stage
    uint32_t aoff, boff[3];
    {
        int mrow = wm * 16 + (li & 1) * 8 + lt;
        aoff = (uint32_t)(mrow * SROW + (li >> 1) * 8) * 2;
    }
#pragma unroll
    for (int q = 0; q < 3; ++q) {
        int nrow = wn * 48 + q * 16 + (li >> 1) * 8 + lt;
        boff[q] = (uint32_t)(A_HALVES + nrow * SROW + (li & 1) * 8) * 2;
    }

    auto loadChunk = [&](int st, int ci) {
        uint32_t sa = sbase + st * STG_GRU;
        int k0 = ci * KC;
        {   // A: 64 rows x 4 x 16B = 256 ops
            int r = tid >> 2, sg = tid & 3;
            cpa16(sa + (r * SROW + sg * 8) * 2,
                  d_iAS + (size_t)(b0 + r) * KS + k0 + sg * 8);
        }
        {   // B: 96 rows x 4 = 384 ops
            int r = tid >> 2, sg = tid & 3;
            int s = r >> 5, jt = r & 31;
            cpa16(sa + A_HALVES * 2 + (r * SROW + sg * 8) * 2,
                  d_WhhS + (size_t)(s * KP + j0 + jt) * KS + k0 + sg * 8);
            if (tid < 128) {
                int idx = tid + 256;
                r = idx >> 2; sg = idx & 3;
                s = r >> 5; jt = r & 31;
                cpa16(sa + A_HALVES * 2 + (r * SROW + sg * 8) * 2,
                      d_WhhS + (size_t)(s * KP + j0 + jt) * KS + k0 + sg * 8);
            }
        }
    };

    loadChunk(0, 0); CP_COMMIT();
    loadChunk(1, 1); CP_COMMIT();
    loadChunk(2, 2); CP_COMMIT();

#pragma unroll 1
    for (int ci = 0; ci < NCH; ++ci) {
        if (ci < NCH - 2) cp_wait<2>(); else if (ci == NCH - 2) cp_wait<1>(); else cp_wait<0>();
        __syncthreads();
        if (ci + 3 < NCH) { loadChunk((ci + 3) & 3, ci + 3); CP_COMMIT(); }
        uint32_t stg = sbase + (ci & 3) * STG_GRU;
#pragma unroll
        for (int k16 = 0; k16 < 2; ++k16) {
            uint32_t ko2 = (uint32_t)k16 * 32;
            uint32_t a[4];
            ldsm4(a, stg + aoff + ko2);
#pragma unroll
            for (int q = 0; q < 3; ++q) {
                uint32_t bb[4];
                ldsm4(bb, stg + boff[q] + ko2);
                mma_bf16(c[2 * q],     a, bb[0], bb[1]);
                mma_bf16(c[2 * q + 1], a, bb[2], bb[3]);
            }
        }
    }

    // ---- epilogue: dump accumulators to smem, then GRU cell ----
    __syncthreads();
    float* cs = (float*)sm;                 // [64][100]
    {
        int g = lane >> 2, tig = lane & 3;
        int row0 = wm * 16 + g;
#pragma unroll
        for (int nf = 0; nf < 6; ++nf) {
            int col = wn * 48 + nf * 8 + 2 * tig;
            *(float2*)&cs[row0 * 100 + col] = make_float2(c[nf][0], c[nf][1]);
            *(float2*)&cs[(row0 + 8) * 100 + col] = make_float2(c[nf][2], c[nf][3]);
        }
    }
    __syncthreads();

#pragma unroll 1
    for (int idx = tid; idx < MB * JT; idx += 256) {
        int r = idx >> 5, j = idx & 31;
        int jg = j0 + j;
        if (jg >= HID) continue;
        int grow = b0 + r;
        int t = types[grow * MAXN + v], p = paths[grow * MAXN + v];
        float rp = cs[r * 100 + j];
        float zp = cs[r * 100 + 32 + j];
        float np = cs[r * 100 + 64 + j];
        float hin = d_hin[(size_t)grow * KP + jg];
        const float* w0 = W_ih + (size_t)jg * 19;
        const float* w1 = W_ih + (size_t)(jg + HID) * 19;
        const float* w2 = W_ih + (size_t)(jg + 2 * HID) * 19;
        float rr = sigm(rp + w0[t] + w0[NT + p] + b_ih[jg] + b_hh[jg]);
        float zz = sigm(zp + w1[t] + w1[NT + p] + b_ih[jg + HID] + b_hh[jg + HID]);
        float nn = tanhf(w2[t] + w2[NT + p] + b_ih[jg + 2 * HID] +
                         rr * (np + b_hh[jg + 2 * HID]));
        float h = (1.f - zz) * nn + zz * hin;
        d_hcur[(size_t)grow * KP + jg] = h;
        __nv_bfloat16 hh, hl; bsplit(h, hh, hl);
        size_t o = (size_t)grow * KS + jg;
        d_hAS[o] = hh; d_hAS[o + KP] = hl; d_hAS[o + 2 * KP] = hh;
    }
}

// ============================================================================
// Fused gate GEMM+epilogue+hin. 64 batch x 32 j x 2 mats, K=960 bf16.
// ============================================================================
__global__ void __launch_bounds__(256, 4) k_ggate(int v,
    const int* __restrict__ paths, const int* __restrict__ adj,
    const float* __restrict__ Wg, const float* __restrict__ bg,
    const float* __restrict__ Wm)
{
    extern __shared__ __nv_bfloat16 sm[];
    float* adjf = (float*)(sm + 4 * (STG_GT / 2));   // [64][12], persists
    int tid = threadIdx.x, lane = tid & 31, wid = tid >> 5;
    int li = lane >> 3, lt = lane & 7;
    int wm = wid >> 1, wn = wid & 1;
    int b0 = blockIdx.x * MB, j0 = blockIdx.y * JT;

    float c[4][4];
#pragma unroll
    for (int nf = 0; nf < 4; ++nf)
#pragma unroll
        for (int i = 0; i < 4; ++i) c[nf][i] = 0.f;

    uint32_t sbase = (uint32_t)__cvta_generic_to_shared(sm);

    uint32_t aoff, boff[2];
    {
        int mrow = wm * 16 + (li & 1) * 8 + lt;
        aoff = (uint32_t)(mrow * SROW + (li >> 1) * 8) * 2;
    }
#pragma unroll
    for (int q = 0; q < 2; ++q) {
        int nrow = wn * 32 + q * 16 + (li >> 1) * 8 + lt;
        boff[q] = (uint32_t)(A_HALVES + nrow * SROW + (li & 1) * 8) * 2;
    }

    auto loadChunk = [&](int st, int ci) {
        uint32_t sa = sbase + st * STG_GT;
        int k0 = ci * KC;
        {   // A: 256 ops
            int r = tid >> 2, sg = tid & 3;
            cpa16(sa + (r * SROW + sg * 8) * 2,
                  d_hAS + (size_t)(b0 + r) * KS + k0 + sg * 8);
        }
        {   // B: 64 rows x 4 = 256 ops
            int r = tid >> 2, sg = tid & 3;
            int s = r >> 5, jt = r & 31;
            cpa16(sa + A_HALVES * 2 + (r * SROW + sg * 8) * 2,
                  d_WgmS + (size_t)(s * KP + j0 + jt) * KS + k0 + sg * 8);
        }
    };

    loadChunk(0, 0); CP_COMMIT();
    loadChunk(1, 1); CP_COMMIT();
    loadChunk(2, 2); CP_COMMIT();
    for (int idx = tid; idx < MB * MAXN; idx += 256) {
        int r = idx / MAXN, u = idx - r * MAXN;
        adjf[idx] = (float)adj[(size_t)(b0 + r) * (MAXN * MAXN) + (v + 1) * MAXN + u];
    }

#pragma unroll 1
    for (int ci = 0; ci < NCH; ++ci) {
        if (ci < NCH - 2) cp_wait<2>(); else if (ci == NCH - 2) cp_wait<1>(); else cp_wait<0>();
        __syncthreads();
        if (ci + 3 < NCH) { loadChunk((ci + 3) & 3, ci + 3); CP_COMMIT(); }
        uint32_t stg = sbase + (ci & 3) * STG_GT;
#pragma unroll
        for (int k16 = 0; k16 < 2; ++k16) {
            uint32_t ko2 = (uint32_t)k16 * 32;
            uint32_t a[4];
            ldsm4(a, stg + aoff + ko2);
#pragma unroll
            for (int q = 0; q < 2; ++q) {
                uint32_t bb[4];
                ldsm4(bb, stg + boff[q] + ko2);
                mma_bf16(c[2 * q],     a, bb[0], bb[1]);
                mma_bf16(c[2 * q + 1], a, bb[2], bb[3]);
            }
        }
    }

    // ---- epilogue via smem ----
    __syncthreads();
    float* cs    = (float*)sm;                 // [64][68]
    float* g_s   = cs + MB * 68;               // [64][32]
    float* hin_s = g_s + MB * JT;              // [64][32]
    {
        int g = lane >> 2, tig = lane & 3;
        int row0 = wm * 16 + g;
#pragma unroll
        for (int nf = 0; nf < 4; ++nf) {
            int col = wn * 32 + nf * 8 + 2 * tig;
            *(float2*)&cs[row0 * 68 + col] = make_float2(c[nf][0], c[nf][1]);
            *(float2*)&cs[(row0 + 8) * 68 + col] = make_float2(c[nf][2], c[nf][3]);
        }
    }
    __syncthreads();

#pragma unroll 1
    for (int idx = tid; idx < MB * JT; idx += 256) {
        int r = idx >> 5, j = idx & 31;
        int jg = j0 + j;
        float val = 0.f;
        if (jg < HID) {
            int p = paths[(b0 + r) * MAXN + v];
            float gv = sigm(cs[r * 68 + j] + Wg[(size_t)jg * VSTAT + HID + p] + bg[jg]);
            float mv = cs[r * 68 + 32 + j] + Wm[(size_t)jg * VSTAT + HID + p];
            val = gv * mv;
        }
        g_s[idx] = val;
    }
    __syncthreads();

    // hin_{v+1}[b, j-slice] = sum_{u<=v} adj[b,v+1,u] * g_u[b, j-slice]
#pragma unroll 1
    for (int idx = tid; idx < MB * JT; idx += 256) {
        int r = idx >> 5, j = idx & 31;
        float acc = 0.f;
        for (int u = 0; u < v; ++u) {
            if (adjf[r * MAXN + u] != 0.f)
                acc += d_g[((size_t)(b0 + r) * 11 + u) * KP + j0 + j];
        }
        if (adjf[r * MAXN + v] != 0.f) acc += g_s[idx];
        hin_s[idx] = acc;
    }
    __syncthreads();

    // coalesced writes: g, hin, iAS splits
#pragma unroll 1
    for (int idx = tid; idx < MB * (JT / 4); idx += 256) {
        int r = idx / (JT / 4), sg = idx - r * (JT / 4);
        float4 g4 = *(float4*)&g_s[r * JT + sg * 4];
        *(float4*)&d_g[((size_t)(b0 + r) * 11 + v) * KP + j0 + sg * 4] = g4;
        float4 h4 = *(float4*)&hin_s[r * JT + sg * 4];
        *(float4*)&d_hin[(size_t)(b0 + r) * KP + j0 + sg * 4] = h4;
        __nv_bfloat16 h0, l0, h1, l1, h2, l2, h3, l3;
        bsplit(h4.x, h0, l0); bsplit(h4.y, h1, l1);
        bsplit(h4.z, h2, l2); bsplit(h4.w, h3, l3);
        size_t o = (size_t)(b0 + r) * KS + j0 + sg * 4;
        __nv_bfloat162* ph_ = (__nv_bfloat162*)(d_iAS + o);
        ph_[0] = __nv_bfloat162{h0, h1}; ph_[1] = __nv_bfloat162{h2, h3};
        __nv_bfloat162* pl_ = (__nv_bfloat162*)(d_iAS + o + KP);
        pl_[0] = __nv_bfloat162{l0, l1}; pl_[1] = __nv_bfloat162{l2, l3};
        __nv_bfloat162* p2_ = (__nv_bfloat162*)(d_iAS + o + 2 * KP);
        p2_[0] = __nv_bfloat162{h0, h1}; p2_[1] = __nv_bfloat162{h2, h3};
    }
}

// ---------------- head ------------------------------------------------------
__global__ void __launch_bounds__(128) k_head(
    const int* __restrict__ paths, const float* __restrict__ feats,
    const float* __restrict__ W_df1, const float* __restrict__ b_df1,
    const float* __restrict__ W_df2, const float* __restrict__ b_df2,
    const float* __restrict__ W_fc1, const float* __restrict__ b_fc1,
    const float* __restrict__ W_fc2, const float* __restrict__ b_fc2,
    float* __restrict__ out)
{
    int b = blockIdx.x;
    int t = threadIdx.x;
    __shared__ float hg[HID + 8];
    __shared__ float df[3 * PP];
    __shared__ float hid16[16];

    for (int j = t; j < HID; j += 128) hg[j] = d_hcur[(size_t)b * KP + j];
    if (t < 3 * PP) df[t] = 0.f;
    __syncthreads();
    if (t == 0) {
        for (int v = 0; v < MAXN; ++v) {
            int base = paths[b * MAXN + v] * 3;
            df[base]     = feats[(b * MAXN + v) * 3 + 0];
            df[base + 1] = feats[(b * MAXN + v) * 3 + 1];
            df[base + 2] = feats[(b * MAXN + v) * 3 + 2];
        }
    }
    __syncthreads();
    if (t < 16) {
        float a = b_df1[t];
        for (int k = 0; k < 3 * PP; ++k) a = fmaf(df[k], W_df1[t * (3 * PP) + k], a);
        hid16[t] = fmaxf(a, 0.f);
    }
    __syncthreads();
    if (t < 8) {
        float a = b_df2[t];
        for (int k = 0; k < 16; ++k) a = fmaf(hid16[k], W_df2[t * 16 + k], a);
        hg[HID + t] = a;
    }
    __syncthreads();
    if (t < 112) {
        const float* W;
        float a;
        int i;
        if (t < 56) { i = t;      W = W_fc1; a = b_fc1[i]; }
        else        { i = t - 56; W = W_fc2; a = b_fc2[i]; }
        const float* wrow = W + i * (HID + 8);
        for (int k = 0; k < HID + 8; ++k) a = fmaf(hg[k], wrow[k], a);
        out[b * 112 + t] = a;
    }
}

// ---------------- launcher --------------------------------------------------
extern "C" void kernel_launch(void* const* d_in, const int* in_sizes, int n_in,
                              void* d_out, int out_size)
{
    const int*   types = (const int*)d_in[0];
    const int*   paths = (const int*)d_in[1];
    const int*   adj   = (const int*)d_in[2];
    const float* feats = (const float*)d_in[3];
    const float* W_ih  = (const float*)d_in[4];
    const float* W_hh  = (const float*)d_in[5];
    const float* b_ih  = (const float*)d_in[6];
    const float* b_hh  = (const float*)d_in[7];
    const float* Wg    = (const float*)d_in[8];
    const float* bg    = (const float*)d_in[9];
    const float* Wm    = (const float*)d_in[10];
    const float* W_df1 = (const float*)d_in[11];
    const float* b_df1 = (const float*)d_in[12];
    const float* W_df2 = (const float*)d_in[13];
    const float* b_df2 = (const float*)d_in[14];
    const float* W_fc1 = (const float*)d_in[15];
    const float* b_fc1 = (const float*)d_in[16];
    const float* W_fc2 = (const float*)d_in[17];
    const float* b_fc2 = (const float*)d_in[18];
    float* out = (float*)d_out;

    cudaFuncSetAttribute(k_ggru,  cudaFuncAttributeMaxDynamicSharedMemorySize, GRU_SMEM);
    cudaFuncSetAttribute(k_ggate, cudaFuncAttributeMaxDynamicSharedMemorySize, GT_SMEM);

    dim3 grid(BB / MB, KP / JT);   // 64 x 10 = 640 blocks

    k_pad<<<(5 * HID * HID + 255) / 256, 256>>>(W_hh, Wg, Wm);
    k_h0<<<(BB * HID + 255) / 256, 256>>>(types, paths, W_ih, b_ih, b_hh);

    k_ggate<<<grid, 256, GT_SMEM>>>(0, paths, adj, Wg, bg, Wm);
    for (int v = 1; v < MAXN; ++v) {
        k_ggru<<<grid, 256, GRU_SMEM>>>(v, types, paths, W_ih, b_ih, b_hh);
        if (v < MAXN - 1)
            k_ggate<<<grid, 256, GT_SMEM>>>(v, paths, adj, Wg, bg, Wm);
    }
    k_head<<<BB, 128>>>(paths, feats, W_df1, b_df1, W_df2, b_df2,
                        W_fc1, b_fc1, W_fc2, b_fc2, out);
}

// round 10
// speedup vs baseline: 1.2136x; 1.2136x over previous
#include <cuda_runtime.h>
#include <cuda_fp16.h>
#include <cstdint>

#define BB 4096
#define MAXN 12
#define HID 301
#define NT 10
#define PP 9
#define VSTAT 310
#define KP 320          // padded hidden
#define KS 640          // K concat: act [hi|lo] fp16, weights [hi|hi] fp16
#define JT 32           // j-cols per block
#define KC 64           // K per chunk
#define NCH 10          // 640/64
#define SROW 72         // smem row stride in halves (144B; conflict-free)

#define A_H (128 * SROW)            // A stage halves
#define BGRU_H (96 * SROW)
#define BGT_H (64 * SROW)
#define STG_GRU ((A_H + BGRU_H) * 2)   // bytes
#define STG_GT  ((A_H + BGT_H) * 2)    // bytes
#define GRU_SMEM (3 * STG_GRU)
#define GT_SMEM  (3 * STG_GT + 128 * MAXN * 4)

// ---------------- scratch (device globals; zero-initialized) ----------------
__device__ __align__(16) float d_g[(size_t)BB * 11 * KP];
__device__ __align__(16) float d_hcur[(size_t)BB * KP];
__device__ __align__(16) float d_hin[(size_t)BB * KP];
__device__ __align__(16) __half d_hAS[(size_t)BB * KS];
__device__ __align__(16) __half d_iAS[(size_t)BB * KS];
__device__ __align__(16) __half d_WhhS[960 * KS];   // rows s*320+j
__device__ __align__(16) __half d_WgmS[640 * KS];   // rows m*320+j

__device__ __forceinline__ float sigm(float x) { return 1.f / (1.f + __expf(-x)); }
__device__ __forceinline__ void hsplit(float x, __half& hi, __half& lo) {
    hi = __float2half_rn(x);
    lo = __float2half_rn(x - __half2float(hi));
}
__device__ __forceinline__ void mma_f16(float c[4], const uint32_t a[4],
                                        uint32_t b0, uint32_t b1) {
    asm volatile(
        "mma.sync.aligned.m16n8k16.row.col.f32.f16.f16.f32 "
        "{%0,%1,%2,%3}, {%4,%5,%6,%7}, {%8,%9}, {%0,%1,%2,%3};"
        : "+f"(c[0]), "+f"(c[1]), "+f"(c[2]), "+f"(c[3])
        : "r"(a[0]), "r"(a[1]), "r"(a[2]), "r"(a[3]), "r"(b0), "r"(b1));
}
__device__ __forceinline__ void ldsm4(uint32_t* r, uint32_t addr) {
    asm volatile("ldmatrix.sync.aligned.m8n8.x4.shared.b16 {%0,%1,%2,%3}, [%4];"
                 : "=r"(r[0]), "=r"(r[1]), "=r"(r[2]), "=r"(r[3]) : "r"(addr));
}
__device__ __forceinline__ void cpa16(uint32_t s, const void* g) {
    asm volatile("cp.async.ca.shared.global [%0], [%1], 16;" :: "r"(s), "l"(g));
}
#define CP_COMMIT() asm volatile("cp.async.commit_group;")
template<int N> __device__ __forceinline__ void cp_wait() {
    asm volatile("cp.async.wait_group %0;" :: "n"(N));
}

// ---------------- weight repack: fp16 round, duplicated segments ------------
__global__ void k_pad(const float* __restrict__ Whh, const float* __restrict__ Wg,
                      const float* __restrict__ Wm)
{
    int idx = blockIdx.x * blockDim.x + threadIdx.x;
    const int total = HID * HID;
    if (idx < 3 * total) {
        int s = idx / total, r = idx - s * total, j = r / HID, k = r - j * HID;
        __half hi = __float2half_rn(Whh[(s * HID + j) * HID + k]);
        size_t row = (size_t)(s * KP + j) * KS;
        d_WhhS[row + k] = hi; d_WhhS[row + KP + k] = hi;
    } else if (idx < 5 * total) {
        int m = (idx - 3 * total) / total, r = (idx - 3 * total) % total;
        int j = r / HID, k = r - j * HID;
        const float* W = m ? Wm : Wg;
        __half hi = __float2half_rn(W[j * VSTAT + k]);
        size_t row = (size_t)(m * KP + j) * KS;
        d_WgmS[row + k] = hi; d_WgmS[row + KP + k] = hi;
    }
}

// ---------------- node 0: h0 = gru(x0, 0) -----------------------------------
__global__ void k_h0(const int* __restrict__ types, const int* __restrict__ paths,
                     const float* __restrict__ W_ih, const float* __restrict__ b_ih,
                     const float* __restrict__ b_hh)
{
    int idx = blockIdx.x * blockDim.x + threadIdx.x;
    if (idx >= BB * HID) return;
    int b = idx / HID, j = idx - b * HID;
    int t = types[b * MAXN], p = paths[b * MAXN];
    float ir  = W_ih[j * 19 + t]            + W_ih[j * 19 + NT + p]            + b_ih[j];
    float iz  = W_ih[(j + HID) * 19 + t]    + W_ih[(j + HID) * 19 + NT + p]    + b_ih[j + HID];
    float inn = W_ih[(j + 2*HID) * 19 + t]  + W_ih[(j + 2*HID) * 19 + NT + p]  + b_ih[j + 2*HID];
    float r = sigm(ir + b_hh[j]);
    float z = sigm(iz + b_hh[j + HID]);
    float n = tanhf(inn + r * b_hh[j + 2*HID]);
    float h = (1.f - z) * n;
    d_hcur[(size_t)b * KP + j] = h;
    __half hi, lo; hsplit(h, hi, lo);
    size_t o = (size_t)b * KS + j;
    d_hAS[o] = hi; d_hAS[o + KP] = lo;
}

// ============================================================================
// Fused GRU GEMM+epilogue. 128 batch x 32 j x 3 gates, K=640 fp16.
// 3-stage cp.async pipeline, ldmatrix fragment loads, early prefetch issue.
// ============================================================================
__global__ void __launch_bounds__(256, 2) k_ggru(int v,
    const int* __restrict__ types, const int* __restrict__ paths,
    const float* __restrict__ W_ih,
    const float* __restrict__ b_ih, const float* __restrict__ b_hh)
{
    extern __shared__ __half sm[];
    int tid = threadIdx.x, lane = tid & 31, wid = tid >> 5;
    int g = lane >> 2, tig = lane & 3;
    int li = lane >> 3, lt = lane & 7;          // ldmatrix row decomposition
    int wm = wid >> 1, wn = wid & 1;
    int b0 = blockIdx.x * 128, j0 = blockIdx.y * JT;

    float c[2][3][2][4];
#pragma unroll
    for (int mf = 0; mf < 2; ++mf)
#pragma unroll
        for (int s = 0; s < 3; ++s)
#pragma unroll
            for (int nf = 0; nf < 2; ++nf)
#pragma unroll
                for (int i = 0; i < 4; ++i) c[mf][s][nf][i] = 0.f;

    uint32_t sbase = (uint32_t)__cvta_generic_to_shared(sm);

    // ldmatrix per-lane byte offsets (within a stage)
    uint32_t aoff[2], boff[3];
#pragma unroll
    for (int mf = 0; mf < 2; ++mf) {
        int mrow = wm * 32 + mf * 16 + (li & 1) * 8 + lt;
        aoff[mf] = (uint32_t)(mrow * SROW + (li >> 1) * 8) * 2;
    }
#pragma unroll
    for (int q = 0; q < 3; ++q) {
        int cmb = 2 * q + (li >> 1);            // combo = s*2+nf
        int s = cmb >> 1, nf = cmb & 1;
        int nrow = s * 32 + wn * 16 + nf * 8 + lt;
        boff[q] = (uint32_t)(A_H + nrow * SROW + (li & 1) * 8) * 2;
    }

    auto loadChunk = [&](int st, int ci) {
        uint32_t sa = sbase + st * STG_GRU;
        uint32_t sbb = sa + A_H * 2;
        int k0 = ci * KC;
#pragma unroll
        for (int q = 0; q < 4; ++q) {
            int idx = tid + 256 * q;
            int r = idx >> 3, sg = idx & 7;
            cpa16(sa + (r * SROW + sg * 8) * 2,
                  d_iAS + (size_t)(b0 + r) * KS + k0 + sg * 8);
        }
#pragma unroll
        for (int q = 0; q < 3; ++q) {
            int idx = tid + 256 * q;
            int r = idx >> 3, sg = idx & 7;
            int s = r >> 5, jt = r & 31;
            cpa16(sbb + (r * SROW + sg * 8) * 2,
                  d_WhhS + (size_t)(s * KP + j0 + jt) * KS + k0 + sg * 8);
        }
    };

    loadChunk(0, 0); CP_COMMIT();
    loadChunk(1, 1); CP_COMMIT();

#pragma unroll 1
    for (int ci = 0; ci < NCH; ++ci) {
        if (ci < NCH - 1) cp_wait<1>(); else cp_wait<0>();
        __syncthreads();
        if (ci + 2 < NCH) { loadChunk((ci + 2) % 3, ci + 2); CP_COMMIT(); }
        uint32_t stg = sbase + (ci % 3) * STG_GRU;
#pragma unroll
        for (int k16 = 0; k16 < 4; ++k16) {
            uint32_t ko2 = (uint32_t)(k16 * 16) * 2;
            uint32_t a0[4], a1[4];
            ldsm4(a0, stg + aoff[0] + ko2);
            ldsm4(a1, stg + aoff[1] + ko2);
#pragma unroll
            for (int q = 0; q < 3; ++q) {
                uint32_t bb[4];
                ldsm4(bb, stg + boff[q] + ko2);
#pragma unroll
                for (int hf = 0; hf < 2; ++hf) {
                    int cmb = 2 * q + hf;
                    int s = cmb >> 1, nf = cmb & 1;
                    mma_f16(c[0][s][nf], a0, bb[2 * hf], bb[2 * hf + 1]);
                    mma_f16(c[1][s][nf], a1, bb[2 * hf], bb[2 * hf + 1]);
                }
            }
        }
    }

    // ---- fused GRU epilogue ----
#pragma unroll
    for (int mf = 0; mf < 2; ++mf) {
#pragma unroll
        for (int hf = 0; hf < 2; ++hf) {
            int row = b0 + wm * 32 + mf * 16 + g + hf * 8;
            int t = types[row * MAXN + v], p = paths[row * MAXN + v];
#pragma unroll
            for (int nf = 0; nf < 2; ++nf) {
                int jb = j0 + wn * 16 + nf * 8 + 2 * tig;
                float h2[2];
#pragma unroll
                for (int cl = 0; cl < 2; ++cl) {
                    int j = jb + cl;
                    int ci2 = hf * 2 + cl;
                    float h = 0.f;
                    if (j < HID) {
                        float hin = d_hin[(size_t)row * KP + j];
                        const float* w0 = W_ih + (size_t)j * 19;
                        const float* w1 = W_ih + (size_t)(j + HID) * 19;
                        const float* w2 = W_ih + (size_t)(j + 2 * HID) * 19;
                        float rr = sigm(c[mf][0][nf][ci2] + w0[t] + w0[NT + p] +
                                        b_ih[j] + b_hh[j]);
                        float zz = sigm(c[mf][1][nf][ci2] + w1[t] + w1[NT + p] +
                                        b_ih[j + HID] + b_hh[j + HID]);
                        float nn = tanhf(w2[t] + w2[NT + p] + b_ih[j + 2 * HID] +
                                         rr * (c[mf][2][nf][ci2] + b_hh[j + 2 * HID]));
                        h = (1.f - zz) * nn + zz * hin;
                    }
                    h2[cl] = h;
                }
                *(float2*)&d_hcur[(size_t)row * KP + jb] = make_float2(h2[0], h2[1]);
                __half h0h, h0l, h1h, h1l;
                hsplit(h2[0], h0h, h0l); hsplit(h2[1], h1h, h1l);
                size_t o = (size_t)row * KS + jb;
                *(__half2*)(d_hAS + o)      = __half2{h0h, h1h};
                *(__half2*)(d_hAS + o + KP) = __half2{h0l, h1l};
            }
        }
    }
}

// ============================================================================
// Fused gate GEMM+epilogue+hin. 128 batch x 32 j x 2 mats, K=640 fp16.
// ============================================================================
__global__ void __launch_bounds__(256, 2) k_ggate(int v,
    const int* __restrict__ paths, const int* __restrict__ adj,
    const float* __restrict__ Wg, const float* __restrict__ bg,
    const float* __restrict__ Wm)
{
    extern __shared__ __half sm[];
    float* adjf = (float*)(sm + 3 * (STG_GT / 2));   // [128][12], persists
    int tid = threadIdx.x, lane = tid & 31, wid = tid >> 5;
    int g = lane >> 2, tig = lane & 3;
    int li = lane >> 3, lt = lane & 7;
    int wm = wid >> 1, wn = wid & 1;
    int b0 = blockIdx.x * 128, j0 = blockIdx.y * JT;

    float c[2][2][2][4];
#pragma unroll
    for (int mf = 0; mf < 2; ++mf)
#pragma unroll
        for (int s = 0; s < 2; ++s)
#pragma unroll
            for (int nf = 0; nf < 2; ++nf)
#pragma unroll
                for (int i = 0; i < 4; ++i) c[mf][s][nf][i] = 0.f;

    uint32_t sbase = (uint32_t)__cvta_generic_to_shared(sm);

    uint32_t aoff[2], boff[2];
#pragma unroll
    for (int mf = 0; mf < 2; ++mf) {
        int mrow = wm * 32 + mf * 16 + (li & 1) * 8 + lt;
        aoff[mf] = (uint32_t)(mrow * SROW + (li >> 1) * 8) * 2;
    }
#pragma unroll
    for (int q = 0; q < 2; ++q) {
        int cmb = 2 * q + (li >> 1);
        int s = cmb >> 1, nf = cmb & 1;
        int nrow = s * 32 + wn * 16 + nf * 8 + lt;
        boff[q] = (uint32_t)(A_H + nrow * SROW + (li & 1) * 8) * 2;
    }

    auto loadChunk = [&](int st, int ci) {
        uint32_t sa = sbase + st * STG_GT;
        uint32_t sbb = sa + A_H * 2;
        int k0 = ci * KC;
#pragma unroll
        for (int q = 0; q < 4; ++q) {
            int idx = tid + 256 * q;
            int r = idx >> 3, sg = idx & 7;
            cpa16(sa + (r * SROW + sg * 8) * 2,
                  d_hAS + (size_t)(b0 + r) * KS + k0 + sg * 8);
        }
#pragma unroll
        for (int q = 0; q < 2; ++q) {
            int idx = tid + 256 * q;
            int r = idx >> 3, sg = idx & 7;
            int s = r >> 5, jt = r & 31;
            cpa16(sbb + (r * SROW + sg * 8) * 2,
                  d_WgmS + (size_t)(s * KP + j0 + jt) * KS + k0 + sg * 8);
        }
    };

    loadChunk(0, 0); CP_COMMIT();
    loadChunk(1, 1); CP_COMMIT();
    for (int idx = tid; idx < 128 * MAXN; idx += 256) {
        int r = idx / MAXN, u = idx - r * MAXN;
        adjf[idx] = (float)adj[(size_t)(b0 + r) * (MAXN * MAXN) + (v + 1) * MAXN + u];
    }

#pragma unroll 1
    for (int ci = 0; ci < NCH; ++ci) {
        if (ci < NCH - 1) cp_wait<1>(); else cp_wait<0>();
        __syncthreads();
        if (ci + 2 < NCH) { loadChunk((ci + 2) % 3, ci + 2); CP_COMMIT(); }
        uint32_t stg = sbase + (ci % 3) * STG_GT;
#pragma unroll
        for (int k16 = 0; k16 < 4; ++k16) {
            uint32_t ko2 = (uint32_t)(k16 * 16) * 2;
            uint32_t a0[4], a1[4];
            ldsm4(a0, stg + aoff[0] + ko2);
            ldsm4(a1, stg + aoff[1] + ko2);
#pragma unroll
            for (int q = 0; q < 2; ++q) {
                uint32_t bb[4];
                ldsm4(bb, stg + boff[q] + ko2);
#pragma unroll
                for (int hf = 0; hf < 2; ++hf) {
                    int cmb = 2 * q + hf;
                    int s = cmb >> 1, nf = cmb & 1;
                    mma_f16(c[0][s][nf], a0, bb[2 * hf], bb[2 * hf + 1]);
                    mma_f16(c[1][s][nf], a1, bb[2 * hf], bb[2 * hf + 1]);
                }
            }
        }
    }

    __syncthreads();                       // stages now dead; reuse for g/hin
    float* g_s   = (float*)sm;             // [128][32]
    float* hin_s = (float*)sm + 128 * JT;  // [128][32]

    // ---- gate epilogue into smem ----
#pragma unroll
    for (int mf = 0; mf < 2; ++mf) {
#pragma unroll
        for (int hf = 0; hf < 2; ++hf) {
            int row = wm * 32 + mf * 16 + g + hf * 8;
            int p = paths[(b0 + row) * MAXN + v];
#pragma unroll
            for (int nf = 0; nf < 2; ++nf) {
                int jl = wn * 16 + nf * 8 + 2 * tig;
#pragma unroll
                for (int cl = 0; cl < 2; ++cl) {
                    int j = j0 + jl + cl;
                    int ci2 = hf * 2 + cl;
                    float val = 0.f;
                    if (j < HID) {
                        float gv = sigm(c[mf][0][nf][ci2] +
                                        Wg[(size_t)j * VSTAT + HID + p] + bg[j]);
                        float mv = c[mf][1][nf][ci2] + Wm[(size_t)j * VSTAT + HID + p];
                        val = gv * mv;
                    }
                    g_s[row * JT + jl + cl] = val;
                }
            }
        }
    }
    __syncthreads();

    // ---- fused hin_{v+1} for this j-slice ----
    for (int idx = tid; idx < 128 * JT; idx += 256) {
        int r = idx / JT, jj = idx - r * JT;
        float acc = 0.f;
        for (int u = 0; u < v; ++u) {
            if (adjf[r * MAXN + u] != 0.f)
                acc += d_g[((size_t)(b0 + r) * 11 + u) * KP + j0 + jj];
        }
        if (adjf[r * MAXN + v] != 0.f) acc += g_s[idx];
        hin_s[idx] = acc;
    }
    __syncthreads();

    // ---- coalesced writes: g, hin, iAS splits ----
    for (int idx = tid; idx < 128 * (JT / 4); idx += 256) {
        int r = idx / (JT / 4), sg = idx - r * (JT / 4);
        float4 g4 = *(float4*)&g_s[r * JT + sg * 4];
        *(float4*)&d_g[((size_t)(b0 + r) * 11 + v) * KP + j0 + sg * 4] = g4;
        float4 h4 = *(float4*)&hin_s[r * JT + sg * 4];
        *(float4*)&d_hin[(size_t)(b0 + r) * KP + j0 + sg * 4] = h4;
        __half h0, l0, h1, l1, h2, l2, h3, l3;
        hsplit(h4.x, h0, l0); hsplit(h4.y, h1, l1);
        hsplit(h4.z, h2, l2); hsplit(h4.w, h3, l3);
        size_t o = (size_t)(b0 + r) * KS + j0 + sg * 4;
        __half2* ph_ = (__half2*)(d_iAS + o);
        ph_[0] = __half2{h0, h1}; ph_[1] = __half2{h2, h3};
        __half2* pl_ = (__half2*)(d_iAS + o + KP);
        pl_[0] = __half2{l0, l1}; pl_[1] = __half2{l2, l3};
    }
}

// ---------------- head ------------------------------------------------------
__global__ void __launch_bounds__(128) k_head(
    const int* __restrict__ paths, const float* __restrict__ feats,
    const float* __restrict__ W_df1, const float* __restrict__ b_df1,
    const float* __restrict__ W_df2, const float* __restrict__ b_df2,
    const float* __restrict__ W_fc1, const float* __restrict__ b_fc1,
    const float* __restrict__ W_fc2, const float* __restrict__ b_fc2,
    float* __restrict__ out)
{
    int b = blockIdx.x;
    int t = threadIdx.x;
    __shared__ float hg[HID + 8];
    __shared__ float df[3 * PP];
    __shared__ float hid16[16];

    for (int j = t; j < HID; j += 128) hg[j] = d_hcur[(size_t)b * KP + j];
    if (t < 3 * PP) df[t] = 0.f;
    __syncthreads();
    if (t == 0) {
        for (int v = 0; v < MAXN; ++v) {
            int base = paths[b * MAXN + v] * 3;
            df[base]     = feats[(b * MAXN + v) * 3 + 0];
            df[base + 1] = feats[(b * MAXN + v) * 3 + 1];
            df[base + 2] = feats[(b * MAXN + v) * 3 + 2];
        }
    }
    __syncthreads();
    if (t < 16) {
        float a = b_df1[t];
        for (int k = 0; k < 3 * PP; ++k) a = fmaf(df[k], W_df1[t * (3 * PP) + k], a);
        hid16[t] = fmaxf(a, 0.f);
    }
    __syncthreads();
    if (t < 8) {
        float a = b_df2[t];
        for (int k = 0; k < 16; ++k) a = fmaf(hid16[k], W_df2[t * 16 + k], a);
        hg[HID + t] = a;
    }
    __syncthreads();
    if (t < 112) {
        const float* W;
        float a;
        int i;
        if (t < 56) { i = t;      W = W_fc1; a = b_fc1[i]; }
        else        { i = t - 56; W = W_fc2; a = b_fc2[i]; }
        const float* wrow = W + i * (HID + 8);
        for (int k = 0; k < HID + 8; ++k) a = fmaf(hg[k], wrow[k], a);
        out[b * 112 + t] = a;
    }
}

// ---------------- launcher --------------------------------------------------
extern "C" void kernel_launch(void* const* d_in, const int* in_sizes, int n_in,
                              void* d_out, int out_size)
{
    const int*   types = (const int*)d_in[0];
    const int*   paths = (const int*)d_in[1];
    const int*   adj   = (const int*)d_in[2];
    const float* feats = (const float*)d_in[3];
    const float* W_ih  = (const float*)d_in[4];
    const float* W_hh  = (const float*)d_in[5];
    const float* b_ih  = (const float*)d_in[6];
    const float* b_hh  = (const float*)d_in[7];
    const float* Wg    = (const float*)d_in[8];
    const float* bg    = (const float*)d_in[9];
    const float* Wm    = (const float*)d_in[10];
    const float* W_df1 = (const float*)d_in[11];
    const float* b_df1 = (const float*)d_in[12];
    const float* W_df2 = (const float*)d_in[13];
    const float* b_df2 = (const float*)d_in[14];
    const float* W_fc1 = (const float*)d_in[15];
    const float* b_fc1 = (const float*)d_in[16];
    const float* W_fc2 = (const float*)d_in[17];
    const float* b_fc2 = (const float*)d_in[18];
    float* out = (float*)d_out;

    cudaFuncSetAttribute(k_ggru,  cudaFuncAttributeMaxDynamicSharedMemorySize, GRU_SMEM);
    cudaFuncSetAttribute(k_ggate, cudaFuncAttributeMaxDynamicSharedMemorySize, GT_SMEM);

    dim3 grid(BB / 128, KP / JT);   // 32 x 10 = 320 blocks

    k_pad<<<(5 * HID * HID + 255) / 256, 256>>>(W_hh, Wg, Wm);
    k_h0<<<(BB * HID + 255) / 256, 256>>>(types, paths, W_ih, b_ih, b_hh);

    k_ggate<<<grid, 256, GT_SMEM>>>(0, paths, adj, Wg, bg, Wm);
    for (int v = 1; v < MAXN; ++v) {
        k_ggru<<<grid, 256, GRU_SMEM>>>(v, types, paths, W_ih, b_ih, b_hh);
        if (v < MAXN - 1)
            k_ggate<<<grid, 256, GT_SMEM>>>(v, paths, adj, Wg, bg, Wm);
    }
    k_head<<<BB, 128>>>(paths, feats, W_df1, b_df1, W_df2, b_df2,
                        W_fc1, b_fc1, W_fc2, b_fc2, out);
}

// round 11
// speedup vs baseline: 1.3856x; 1.1418x over previous
#include <cuda_runtime.h>
#include <cuda_fp16.h>
#include <cstdint>

#define BB 4096
#define MAXN 12
#define HID 301
#define NT 10
#define PP 9
#define VSTAT 310
#define KP 320          // padded hidden
#define KS 640          // K concat: act [hi|lo] fp16, weights [hi|hi] fp16
#define JT 40           // j-cols per block  -> grid 32 x 8 = 256 (single wave)
#define KC 64           // K per chunk
#define NCH 10          // 640/64
#define SROW 72         // smem row stride in halves (144B; conflict-free)

#define A_H (128 * SROW)            // A stage halves
#define BGRU_ROWS 120               // 3 gates * 40
#define BGT_ROWS 80                 // 2 mats * 40
#define STG_GRU ((128 + BGRU_ROWS) * SROW * 2)   // 35712 B
#define STG_GT  ((128 + BGT_ROWS) * SROW * 2)    // 29952 B
#define GRU_SMEM (3 * STG_GRU)                   // 107136
#define GT_SMEM  (3 * STG_GT + 128 * MAXN * 4)   // 96000

// ---------------- scratch (device globals; zero-initialized) ----------------
__device__ __align__(16) float d_g[(size_t)BB * 11 * KP];
__device__ __align__(16) float d_hcur[(size_t)BB * KP];
__device__ __align__(16) float d_hin[(size_t)BB * KP];
__device__ __align__(16) __half d_hAS[(size_t)BB * KS];
__device__ __align__(16) __half d_iAS[(size_t)BB * KS];
__device__ __align__(16) __half d_WhhS[960 * KS];   // rows s*320+j
__device__ __align__(16) __half d_WgmS[640 * KS];   // rows m*320+j

__device__ __forceinline__ float sigm(float x) { return 1.f / (1.f + __expf(-x)); }
__device__ __forceinline__ void hsplit(float x, __half& hi, __half& lo) {
    hi = __float2half_rn(x);
    lo = __float2half_rn(x - __half2float(hi));
}
__device__ __forceinline__ void mma_f16(float c[4], const uint32_t a[4],
                                        uint32_t b0, uint32_t b1) {
    asm volatile(
        "mma.sync.aligned.m16n8k16.row.col.f32.f16.f16.f32 "
        "{%0,%1,%2,%3}, {%4,%5,%6,%7}, {%8,%9}, {%0,%1,%2,%3};"
        : "+f"(c[0]), "+f"(c[1]), "+f"(c[2]), "+f"(c[3])
        : "r"(a[0]), "r"(a[1]), "r"(a[2]), "r"(a[3]), "r"(b0), "r"(b1));
}
__device__ __forceinline__ void ldsm4(uint32_t* r, uint32_t addr) {
    asm volatile("ldmatrix.sync.aligned.m8n8.x4.shared.b16 {%0,%1,%2,%3}, [%4];"
                 : "=r"(r[0]), "=r"(r[1]), "=r"(r[2]), "=r"(r[3]) : "r"(addr));
}
__device__ __forceinline__ void ldsm2(uint32_t* r, uint32_t addr) {
    asm volatile("ldmatrix.sync.aligned.m8n8.x2.shared.b16 {%0,%1}, [%2];"
                 : "=r"(r[0]), "=r"(r[1]) : "r"(addr));
}
__device__ __forceinline__ void cpa16(uint32_t s, const void* g) {
    asm volatile("cp.async.ca.shared.global [%0], [%1], 16;" :: "r"(s), "l"(g));
}
#define CP_COMMIT() asm volatile("cp.async.commit_group;")
template<int N> __device__ __forceinline__ void cp_wait() {
    asm volatile("cp.async.wait_group %0;" :: "n"(N));
}

// ---------------- weight repack: fp16 round, duplicated segments ------------
__global__ void k_pad(const float* __restrict__ Whh, const float* __restrict__ Wg,
                      const float* __restrict__ Wm)
{
    int idx = blockIdx.x * blockDim.x + threadIdx.x;
    const int total = HID * HID;
    if (idx < 3 * total) {
        int s = idx / total, r = idx - s * total, j = r / HID, k = r - j * HID;
        __half hi = __float2half_rn(Whh[(s * HID + j) * HID + k]);
        size_t row = (size_t)(s * KP + j) * KS;
        d_WhhS[row + k] = hi; d_WhhS[row + KP + k] = hi;
    } else if (idx < 5 * total) {
        int m = (idx - 3 * total) / total, r = (idx - 3 * total) % total;
        int j = r / HID, k = r - j * HID;
        const float* W = m ? Wm : Wg;
        __half hi = __float2half_rn(W[j * VSTAT + k]);
        size_t row = (size_t)(m * KP + j) * KS;
        d_WgmS[row + k] = hi; d_WgmS[row + KP + k] = hi;
    }
}

// ---------------- node 0: h0 = gru(x0, 0) -----------------------------------
__global__ void k_h0(const int* __restrict__ types, const int* __restrict__ paths,
                     const float* __restrict__ W_ih, const float* __restrict__ b_ih,
                     const float* __restrict__ b_hh)
{
    int idx = blockIdx.x * blockDim.x + threadIdx.x;
    if (idx >= BB * HID) return;
    int b = idx / HID, j = idx - b * HID;
    int t = types[b * MAXN], p = paths[b * MAXN];
    float ir  = W_ih[j * 19 + t]            + W_ih[j * 19 + NT + p]            + b_ih[j];
    float iz  = W_ih[(j + HID) * 19 + t]    + W_ih[(j + HID) * 19 + NT + p]    + b_ih[j + HID];
    float inn = W_ih[(j + 2*HID) * 19 + t]  + W_ih[(j + 2*HID) * 19 + NT + p]  + b_ih[j + 2*HID];
    float r = sigm(ir + b_hh[j]);
    float z = sigm(iz + b_hh[j + HID]);
    float n = tanhf(inn + r * b_hh[j + 2*HID]);
    float h = (1.f - z) * n;
    d_hcur[(size_t)b * KP + j] = h;
    __half hi, lo; hsplit(h, hi, lo);
    size_t o = (size_t)b * KS + j;
    d_hAS[o] = hi; d_hAS[o + KP] = lo;
}

// ============================================================================
// Fused GRU GEMM+epilogue. 128 batch x 40 j x 3 gates, K=640 fp16.
// Warp layout 8M x 1N (warp: 16 rows x 120 n-cols = 15 n-frags).
// Column jj, jj+40, jj+80 land in the SAME thread -> register-resident GRU.
// ============================================================================
__global__ void __launch_bounds__(256, 2) k_ggru(int v,
    const int* __restrict__ types, const int* __restrict__ paths,
    const float* __restrict__ W_ih,
    const float* __restrict__ b_ih, const float* __restrict__ b_hh)
{
    extern __shared__ __half sm[];
    int tid = threadIdx.x, lane = tid & 31, wid = tid >> 5;
    int g = lane >> 2, tig = lane & 3;
    int li = lane >> 3, lt = lane & 7;
    int b0 = blockIdx.x * 128, j0 = blockIdx.y * JT;

    float c[15][4];
#pragma unroll
    for (int nf = 0; nf < 15; ++nf)
#pragma unroll
        for (int i = 0; i < 4; ++i) c[nf][i] = 0.f;

    uint32_t sbase = (uint32_t)__cvta_generic_to_shared(sm);

    // ldmatrix per-lane byte offsets (within a stage)
    uint32_t aoff, boff[7], boff14;
    {
        int mrow = wid * 16 + (li & 1) * 8 + lt;
        aoff = (uint32_t)(mrow * SROW + (li >> 1) * 8) * 2;
    }
#pragma unroll
    for (int q = 0; q < 7; ++q) {
        int nrow = q * 16 + (li >> 1) * 8 + lt;
        boff[q] = (uint32_t)(A_H + nrow * SROW + (li & 1) * 8) * 2;
    }
    boff14 = (uint32_t)(A_H + (112 + lt) * SROW + ((lane >> 3) & 1) * 8) * 2;

    auto loadChunk = [&](int st, int ci) {
        uint32_t sa = sbase + st * STG_GRU;
        uint32_t sbb = sa + A_H * 2;
        int k0 = ci * KC;
#pragma unroll
        for (int q = 0; q < 4; ++q) {           // A: 128 rows x 8 segs
            int idx = tid + 256 * q;
            int r = idx >> 3, sg = idx & 7;
            cpa16(sa + (r * SROW + sg * 8) * 2,
                  d_iAS + (size_t)(b0 + r) * KS + k0 + sg * 8);
        }
#pragma unroll
        for (int q = 0; q < 4; ++q) {           // B: 120 rows x 8 segs = 960
            int idx = tid + 256 * q;
            if (idx < 960) {
                int r = idx >> 3, sg = idx & 7;
                int s = r / JT, jt = r - s * JT;
                cpa16(sbb + (r * SROW + sg * 8) * 2,
                      d_WhhS + (size_t)(s * KP + j0 + jt) * KS + k0 + sg * 8);
            }
        }
    };

    loadChunk(0, 0); CP_COMMIT();
    loadChunk(1, 1); CP_COMMIT();

#pragma unroll 1
    for (int ci = 0; ci < NCH; ++ci) {
        if (ci < NCH - 1) cp_wait<1>(); else cp_wait<0>();
        __syncthreads();
        if (ci + 2 < NCH) { loadChunk((ci + 2) % 3, ci + 2); CP_COMMIT(); }
        uint32_t stg = sbase + (ci % 3) * STG_GRU;
#pragma unroll
        for (int k16 = 0; k16 < 4; ++k16) {
            uint32_t ko2 = (uint32_t)(k16 * 16) * 2;
            uint32_t a[4];
            ldsm4(a, stg + aoff + ko2);
#pragma unroll
            for (int q = 0; q < 7; ++q) {
                uint32_t bb[4];
                ldsm4(bb, stg + boff[q] + ko2);
                mma_f16(c[2 * q],     a, bb[0], bb[1]);
                mma_f16(c[2 * q + 1], a, bb[2], bb[3]);
            }
            uint32_t b2[2];
            ldsm2(b2, stg + boff14 + ko2);
            mma_f16(c[14], a, b2[0], b2[1]);
        }
    }

    // ---- fused GRU epilogue (r/z/n register-resident: c[nf], c[nf+5], c[nf+10])
#pragma unroll
    for (int hf = 0; hf < 2; ++hf) {
        int row = b0 + wid * 16 + g + hf * 8;
        int t = types[row * MAXN + v], p = paths[row * MAXN + v];
#pragma unroll
        for (int nf = 0; nf < 5; ++nf) {
            int jb = j0 + nf * 8 + 2 * tig;
            float h2[2];
#pragma unroll
            for (int cl = 0; cl < 2; ++cl) {
                int j = jb + cl;
                int ci2 = hf * 2 + cl;
                float h = 0.f;
                if (j < HID) {
                    float hin = d_hin[(size_t)row * KP + j];
                    const float* w0 = W_ih + (size_t)j * 19;
                    const float* w1 = W_ih + (size_t)(j + HID) * 19;
                    const float* w2 = W_ih + (size_t)(j + 2 * HID) * 19;
                    float rr = sigm(c[nf][ci2] + w0[t] + w0[NT + p] +
                                    b_ih[j] + b_hh[j]);
                    float zz = sigm(c[nf + 5][ci2] + w1[t] + w1[NT + p] +
                                    b_ih[j + HID] + b_hh[j + HID]);
                    float nn = tanhf(w2[t] + w2[NT + p] + b_ih[j + 2 * HID] +
                                     rr * (c[nf + 10][ci2] + b_hh[j + 2 * HID]));
                    h = (1.f - zz) * nn + zz * hin;
                }
                h2[cl] = h;
            }
            *(float2*)&d_hcur[(size_t)row * KP + jb] = make_float2(h2[0], h2[1]);
            __half h0h, h0l, h1h, h1l;
            hsplit(h2[0], h0h, h0l); hsplit(h2[1], h1h, h1l);
            size_t o = (size_t)row * KS + jb;
            *(__half2*)(d_hAS + o)      = __half2{h0h, h1h};
            *(__half2*)(d_hAS + o + KP) = __half2{h0l, h1l};
        }
    }
}

// ============================================================================
// Fused gate GEMM+epilogue+hin. 128 batch x 40 j x 2 mats, K=640 fp16.
// Warp 8M x 1N: 10 n-frags; g/m pairs in same thread (c[nf], c[nf+5]).
// ============================================================================
__global__ void __launch_bounds__(256, 2) k_ggate(int v,
    const int* __restrict__ paths, const int* __restrict__ adj,
    const float* __restrict__ Wg, const float* __restrict__ bg,
    const float* __restrict__ Wm)
{
    extern __shared__ __half sm[];
    float* adjf = (float*)((char*)sm + 3 * STG_GT);   // [128][12], persists
    int tid = threadIdx.x, lane = tid & 31, wid = tid >> 5;
    int g = lane >> 2, tig = lane & 3;
    int li = lane >> 3, lt = lane & 7;
    int b0 = blockIdx.x * 128, j0 = blockIdx.y * JT;

    float c[10][4];
#pragma unroll
    for (int nf = 0; nf < 10; ++nf)
#pragma unroll
        for (int i = 0; i < 4; ++i) c[nf][i] = 0.f;

    uint32_t sbase = (uint32_t)__cvta_generic_to_shared(sm);

    uint32_t aoff, boff[5];
    {
        int mrow = wid * 16 + (li & 1) * 8 + lt;
        aoff = (uint32_t)(mrow * SROW + (li >> 1) * 8) * 2;
    }
#pragma unroll
    for (int q = 0; q < 5; ++q) {
        int nrow = q * 16 + (li >> 1) * 8 + lt;
        boff[q] = (uint32_t)(A_H + nrow * SROW + (li & 1) * 8) * 2;
    }

    auto loadChunk = [&](int st, int ci) {
        uint32_t sa = sbase + st * STG_GT;
        uint32_t sbb = sa + A_H * 2;
        int k0 = ci * KC;
#pragma unroll
        for (int q = 0; q < 4; ++q) {           // A: 1024 ops
            int idx = tid + 256 * q;
            int r = idx >> 3, sg = idx & 7;
            cpa16(sa + (r * SROW + sg * 8) * 2,
                  d_hAS + (size_t)(b0 + r) * KS + k0 + sg * 8);
        }
#pragma unroll
        for (int q = 0; q < 3; ++q) {           // B: 80 rows x 8 = 640
            int idx = tid + 256 * q;
            if (idx < 640) {
                int r = idx >> 3, sg = idx & 7;
                int s = r / JT, jt = r - s * JT;
                cpa16(sbb + (r * SROW + sg * 8) * 2,
                      d_WgmS + (size_t)(s * KP + j0 + jt) * KS + k0 + sg * 8);
            }
        }
    };

    loadChunk(0, 0); CP_COMMIT();
    loadChunk(1, 1); CP_COMMIT();
    for (int idx = tid; idx < 128 * MAXN; idx += 256) {
        int r = idx / MAXN, u = idx - r * MAXN;
        adjf[idx] = (float)adj[(size_t)(b0 + r) * (MAXN * MAXN) + (v + 1) * MAXN + u];
    }

#pragma unroll 1
    for (int ci = 0; ci < NCH; ++ci) {
        if (ci < NCH - 1) cp_wait<1>(); else cp_wait<0>();
        __syncthreads();
        if (ci + 2 < NCH) { loadChunk((ci + 2) % 3, ci + 2); CP_COMMIT(); }
        uint32_t stg = sbase + (ci % 3) * STG_GT;
#pragma unroll
        for (int k16 = 0; k16 < 4; ++k16) {
            uint32_t ko2 = (uint32_t)(k16 * 16) * 2;
            uint32_t a[4];
            ldsm4(a, stg + aoff + ko2);
#pragma unroll
            for (int q = 0; q < 5; ++q) {
                uint32_t bb[4];
                ldsm4(bb, stg + boff[q] + ko2);
                mma_f16(c[2 * q],     a, bb[0], bb[1]);
                mma_f16(c[2 * q + 1], a, bb[2], bb[3]);
            }
        }
    }

    __syncthreads();                       // stages now dead; reuse for g/hin
    float* g_s   = (float*)sm;             // [128][40]
    float* hin_s = (float*)sm + 128 * JT;  // [128][40]

    // ---- gate epilogue into smem (g/m pairs: c[nf], c[nf+5]) ----
#pragma unroll
    for (int hf = 0; hf < 2; ++hf) {
        int row = wid * 16 + g + hf * 8;
        int p = paths[(b0 + row) * MAXN + v];
#pragma unroll
        for (int nf = 0; nf < 5; ++nf) {
            int jl = nf * 8 + 2 * tig;
#pragma unroll
            for (int cl = 0; cl < 2; ++cl) {
                int j = j0 + jl + cl;
                int ci2 = hf * 2 + cl;
                float val = 0.f;
                if (j < HID) {
                    float gv = sigm(c[nf][ci2] +
                                    Wg[(size_t)j * VSTAT + HID + p] + bg[j]);
                    float mv = c[nf + 5][ci2] + Wm[(size_t)j * VSTAT + HID + p];
                    val = gv * mv;
                }
                g_s[row * JT + jl + cl] = val;
            }
        }
    }
    __syncthreads();

    // ---- fused hin_{v+1} for this j-slice ----
    for (int idx = tid; idx < 128 * JT; idx += 256) {
        int r = idx / JT, jj = idx - r * JT;
        float acc = 0.f;
        for (int u = 0; u < v; ++u) {
            if (adjf[r * MAXN + u] != 0.f)
                acc += d_g[((size_t)(b0 + r) * 11 + u) * KP + j0 + jj];
        }
        if (adjf[r * MAXN + v] != 0.f) acc += g_s[idx];
        hin_s[idx] = acc;
    }
    __syncthreads();

    // ---- coalesced writes: g, hin, iAS splits ----
    for (int idx = tid; idx < 128 * (JT / 4); idx += 256) {
        int r = idx / (JT / 4), sg = idx - r * (JT / 4);
        float4 g4 = *(float4*)&g_s[r * JT + sg * 4];
        *(float4*)&d_g[((size_t)(b0 + r) * 11 + v) * KP + j0 + sg * 4] = g4;
        float4 h4 = *(float4*)&hin_s[r * JT + sg * 4];
        *(float4*)&d_hin[(size_t)(b0 + r) * KP + j0 + sg * 4] = h4;
        __half h0, l0, h1, l1, h2, l2, h3, l3;
        hsplit(h4.x, h0, l0); hsplit(h4.y, h1, l1);
        hsplit(h4.z, h2, l2); hsplit(h4.w, h3, l3);
        size_t o = (size_t)(b0 + r) * KS + j0 + sg * 4;
        __half2* ph_ = (__half2*)(d_iAS + o);
        ph_[0] = __half2{h0, h1}; ph_[1] = __half2{h2, h3};
        __half2* pl_ = (__half2*)(d_iAS + o + KP);
        pl_[0] = __half2{l0, l1}; pl_[1] = __half2{l2, l3};
    }
}

// ---------------- head ------------------------------------------------------
__global__ void __launch_bounds__(128) k_head(
    const int* __restrict__ paths, const float* __restrict__ feats,
    const float* __restrict__ W_df1, const float* __restrict__ b_df1,
    const float* __restrict__ W_df2, const float* __restrict__ b_df2,
    const float* __restrict__ W_fc1, const float* __restrict__ b_fc1,
    const float* __restrict__ W_fc2, const float* __restrict__ b_fc2,
    float* __restrict__ out)
{
    int b = blockIdx.x;
    int t = threadIdx.x;
    __shared__ float hg[HID + 8];
    __shared__ float df[3 * PP];
    __shared__ float hid16[16];

    for (int j = t; j < HID; j += 128) hg[j] = d_hcur[(size_t)b * KP + j];
    if (t < 3 * PP) df[t] = 0.f;
    __syncthreads();
    if (t == 0) {
        for (int v = 0; v < MAXN; ++v) {
            int base = paths[b * MAXN + v] * 3;
            df[base]     = feats[(b * MAXN + v) * 3 + 0];
            df[base + 1] = feats[(b * MAXN + v) * 3 + 1];
            df[base + 2] = feats[(b * MAXN + v) * 3 + 2];
        }
    }
    __syncthreads();
    if (t < 16) {
        float a = b_df1[t];
        for (int k = 0; k < 3 * PP; ++k) a = fmaf(df[k], W_df1[t * (3 * PP) + k], a);
        hid16[t] = fmaxf(a, 0.f);
    }
    __syncthreads();
    if (t < 8) {
        float a = b_df2[t];
        for (int k = 0; k < 16; ++k) a = fmaf(hid16[k], W_df2[t * 16 + k], a);
        hg[HID + t] = a;
    }
    __syncthreads();
    if (t < 112) {
        const float* W;
        float a;
        int i;
        if (t < 56) { i = t;      W = W_fc1; a = b_fc1[i]; }
        else        { i = t - 56; W = W_fc2; a = b_fc2[i]; }
        const float* wrow = W + i * (HID + 8);
        for (int k = 0; k < HID + 8; ++k) a = fmaf(hg[k], wrow[k], a);
        out[b * 112 + t] = a;
    }
}

// ---------------- launcher --------------------------------------------------
extern "C" void kernel_launch(void* const* d_in, const int* in_sizes, int n_in,
                              void* d_out, int out_size)
{
    const int*   types = (const int*)d_in[0];
    const int*   paths = (const int*)d_in[1];
    const int*   adj   = (const int*)d_in[2];
    const float* feats = (const float*)d_in[3];
    const float* W_ih  = (const float*)d_in[4];
    const float* W_hh  = (const float*)d_in[5];
    const float* b_ih  = (const float*)d_in[6];
    const float* b_hh  = (const float*)d_in[7];
    const float* Wg    = (const float*)d_in[8];
    const float* bg    = (const float*)d_in[9];
    const float* Wm    = (const float*)d_in[10];
    const float* W_df1 = (const float*)d_in[11];
    const float* b_df1 = (const float*)d_in[12];
    const float* W_df2 = (const float*)d_in[13];
    const float* b_df2 = (const float*)d_in[14];
    const float* W_fc1 = (const float*)d_in[15];
    const float* b_fc1 = (const float*)d_in[16];
    const float* W_fc2 = (const float*)d_in[17];
    const float* b_fc2 = (const float*)d_in[18];
    float* out = (float*)d_out;

    cudaFuncSetAttribute(k_ggru,  cudaFuncAttributeMaxDynamicSharedMemorySize, GRU_SMEM);
    cudaFuncSetAttribute(k_ggate, cudaFuncAttributeMaxDynamicSharedMemorySize, GT_SMEM);

    dim3 grid(BB / 128, KP / JT);   // 32 x 8 = 256 blocks (single wave @ occ 2)

    k_pad<<<(5 * HID * HID + 255) / 256, 256>>>(W_hh, Wg, Wm);
    k_h0<<<(BB * HID + 255) / 256, 256>>>(types, paths, W_ih, b_ih, b_hh);

    k_ggate<<<grid, 256, GT_SMEM>>>(0, paths, adj, Wg, bg, Wm);
    for (int v = 1; v < MAXN; ++v) {
        k_ggru<<<grid, 256, GRU_SMEM>>>(v, types, paths, W_ih, b_ih, b_hh);
        if (v < MAXN - 1)
            k_ggate<<<grid, 256, GT_SMEM>>>(v, paths, adj, Wg, bg, Wm);
    }
    k_head<<<BB, 128>>>(paths, feats, W_df1, b_df1, W_df2, b_df2,
                        W_fc1, b_fc1, W_fc2, b_fc2, out);
}

// round 12
// speedup vs baseline: 1.5595x; 1.1255x over previous
#include <cuda_runtime.h>
#include <cuda_fp16.h>
#include <cstdint>

#define BB 4096
#define MAXN 12
#define HID 301
#define NT 10
#define PP 9
#define VSTAT 310
#define KP 320          // padded hidden (= unique K)
#define KS 640          // activation storage: [hi(320) | lo(320)] fp16
#define JT 40           // j-cols per block  -> grid 32 x 8 = 256 (single wave)
#define KC 32           // unique-K per chunk
#define NCH 10          // 320/32
#define SROW 40         // smem row stride in halves (80B; ldsm conflict-free)

#define A1_H (128 * SROW)                       // one A half-tile (halves)
#define STG_GRU ((2 * A1_H + 120 * SROW) * 2)   // 30080 B
#define STG_GT  ((2 * A1_H + 80 * SROW) * 2)    // 26880 B
#define GRU_SMEM (3 * STG_GRU)                  // 90240
#define GT_SMEM  (3 * STG_GT + 128 * MAXN * 4)  // 86784

// ---------------- scratch (device globals; zero-initialized) ----------------
__device__ __align__(16) float d_g[(size_t)BB * 11 * KP];
__device__ __align__(16) float d_hcur[(size_t)BB * KP];
__device__ __align__(16) float d_hin[(size_t)BB * KP];
__device__ __align__(16) __half d_hAS[(size_t)BB * KS];
__device__ __align__(16) __half d_iAS[(size_t)BB * KS];
__device__ __align__(16) __half d_WhhS[960 * KP];   // UNIQUE K=320, rows s*320+j
__device__ __align__(16) __half d_WgmS[640 * KP];   // rows m*320+j
// epilogue tables (coalesced in j)
__device__ __align__(16) float d_T1[NT * 3 * KP];   // W_ih[.,t] + b_ih
__device__ __align__(16) float d_T2[PP * 3 * KP];   // W_ih[.,NT+p]
__device__ __align__(16) float d_bhh3[3 * KP];
__device__ __align__(16) float d_Tg[PP * KP];       // Wg[.,HID+p] + bg
__device__ __align__(16) float d_Tm[PP * KP];       // Wm[.,HID+p]

__device__ __forceinline__ float sigm(float x) { return 1.f / (1.f + __expf(-x)); }
__device__ __forceinline__ void hsplit(float x, __half& hi, __half& lo) {
    hi = __float2half_rn(x);
    lo = __float2half_rn(x - __half2float(hi));
}
__device__ __forceinline__ void mma_f16(float c[4], const uint32_t a[4],
                                        uint32_t b0, uint32_t b1) {
    asm volatile(
        "mma.sync.aligned.m16n8k16.row.col.f32.f16.f16.f32 "
        "{%0,%1,%2,%3}, {%4,%5,%6,%7}, {%8,%9}, {%0,%1,%2,%3};"
        : "+f"(c[0]), "+f"(c[1]), "+f"(c[2]), "+f"(c[3])
        : "r"(a[0]), "r"(a[1]), "r"(a[2]), "r"(a[3]), "r"(b0), "r"(b1));
}
__device__ __forceinline__ void ldsm4(uint32_t* r, uint32_t addr) {
    asm volatile("ldmatrix.sync.aligned.m8n8.x4.shared.b16 {%0,%1,%2,%3}, [%4];"
                 : "=r"(r[0]), "=r"(r[1]), "=r"(r[2]), "=r"(r[3]) : "r"(addr));
}
__device__ __forceinline__ void ldsm2(uint32_t* r, uint32_t addr) {
    asm volatile("ldmatrix.sync.aligned.m8n8.x2.shared.b16 {%0,%1}, [%2];"
                 : "=r"(r[0]), "=r"(r[1]) : "r"(addr));
}
__device__ __forceinline__ void cpa16(uint32_t s, const void* g) {
    asm volatile("cp.async.ca.shared.global [%0], [%1], 16;" :: "r"(s), "l"(g));
}
#define CP_COMMIT() asm volatile("cp.async.commit_group;")
template<int N> __device__ __forceinline__ void cp_wait() {
    asm volatile("cp.async.wait_group %0;" :: "n"(N));
}

// ---------------- weight repack (fp16, UNIQUE K) ----------------------------
__global__ void k_pad(const float* __restrict__ Whh, const float* __restrict__ Wg,
                      const float* __restrict__ Wm)
{
    int idx = blockIdx.x * blockDim.x + threadIdx.x;
    const int total = HID * HID;
    if (idx < 3 * total) {
        int s = idx / total, r = idx - s * total, j = r / HID, k = r - j * HID;
        d_WhhS[(size_t)(s * KP + j) * KP + k] = __float2half_rn(Whh[(s * HID + j) * HID + k]);
    } else if (idx < 5 * total) {
        int m = (idx - 3 * total) / total, r = (idx - 3 * total) % total;
        int j = r / HID, k = r - j * HID;
        const float* W = m ? Wm : Wg;
        d_WgmS[(size_t)(m * KP + j) * KP + k] = __float2half_rn(W[j * VSTAT + k]);
    }
}

// ---------------- epilogue table build --------------------------------------
__global__ void k_tab(const float* __restrict__ W_ih, const float* __restrict__ b_ih,
                      const float* __restrict__ b_hh,
                      const float* __restrict__ Wg, const float* __restrict__ bg,
                      const float* __restrict__ Wm)
{
    int idx = blockIdx.x * blockDim.x + threadIdx.x;
    const int TPK = 3 * KP;
    if (idx < NT * TPK) {
        int t = idx / TPK, r = idx - t * TPK, s = r / KP, j = r - s * KP;
        d_T1[idx] = (j < HID) ? W_ih[(size_t)(s * HID + j) * 19 + t] + b_ih[s * HID + j] : 0.f;
    } else if (idx < NT * TPK + PP * TPK) {
        int q = idx - NT * TPK;
        int p = q / TPK, r = q - p * TPK, s = r / KP, j = r - s * KP;
        d_T2[q] = (j < HID) ? W_ih[(size_t)(s * HID + j) * 19 + NT + p] : 0.f;
    } else if (idx < NT * TPK + PP * TPK + TPK) {
        int q = idx - NT * TPK - PP * TPK;
        int s = q / KP, j = q - s * KP;
        d_bhh3[q] = (j < HID) ? b_hh[s * HID + j] : 0.f;
    } else if (idx < NT * TPK + PP * TPK + TPK + PP * KP) {
        int q = idx - NT * TPK - PP * TPK - TPK;
        int p = q / KP, j = q - p * KP;
        d_Tg[q] = (j < HID) ? Wg[(size_t)j * VSTAT + HID + p] + bg[j] : 0.f;
    } else if (idx < NT * TPK + PP * TPK + TPK + 2 * PP * KP) {
        int q = idx - NT * TPK - PP * TPK - TPK - PP * KP;
        int p = q / KP, j = q - p * KP;
        d_Tm[q] = (j < HID) ? Wm[(size_t)j * VSTAT + HID + p] : 0.f;
    }
}

// ---------------- node 0: h0 = gru(x0, 0) -----------------------------------
__global__ void k_h0(const int* __restrict__ types, const int* __restrict__ paths)
{
    int idx = blockIdx.x * blockDim.x + threadIdx.x;
    if (idx >= BB * HID) return;
    int b = idx / HID, j = idx - b * HID;
    int t = types[b * MAXN], p = paths[b * MAXN];
    const float* t1 = d_T1 + t * 3 * KP;
    const float* t2 = d_T2 + p * 3 * KP;
    float r = sigm(t1[j] + t2[j] + d_bhh3[j]);
    float z = sigm(t1[KP + j] + t2[KP + j] + d_bhh3[KP + j]);
    float n = tanhf(t1[2 * KP + j] + t2[2 * KP + j] + r * d_bhh3[2 * KP + j]);
    float h = (1.f - z) * n;
    d_hcur[(size_t)b * KP + j] = h;
    __half hi, lo; hsplit(h, hi, lo);
    size_t o = (size_t)b * KS + j;
    d_hAS[o] = hi; d_hAS[o + KP] = lo;
}

// ============================================================================
// Fused GRU GEMM+epilogue. 128 batch x 40 j x 3 gates.
// Unique-K=320 loop: B loaded/ldsm'd ONCE, dual mma pass (A_hi, A_lo).
// ============================================================================
__global__ void __launch_bounds__(256, 2) k_ggru(int v,
    const int* __restrict__ types, const int* __restrict__ paths)
{
    extern __shared__ __half sm[];
    int tid = threadIdx.x, lane = tid & 31, wid = tid >> 5;
    int g = lane >> 2, tig = lane & 3;
    int li = lane >> 3, lt = lane & 7;
    int b0 = blockIdx.x * 128, j0 = blockIdx.y * JT;

    float c[15][4];
#pragma unroll
    for (int nf = 0; nf < 15; ++nf)
#pragma unroll
        for (int i = 0; i < 4; ++i) c[nf][i] = 0.f;

    uint32_t sbase = (uint32_t)__cvta_generic_to_shared(sm);

    uint32_t aoffH, aoffL, boff[7], boff14;
    {
        int mrow = wid * 16 + (li & 1) * 8 + lt;
        aoffH = (uint32_t)(mrow * SROW + (li >> 1) * 8) * 2;
        aoffL = aoffH + A1_H * 2;
    }
#pragma unroll
    for (int q = 0; q < 7; ++q) {
        int nrow = q * 16 + (li >> 1) * 8 + lt;
        boff[q] = (uint32_t)(2 * A1_H + nrow * SROW + (li & 1) * 8) * 2;
    }
    boff14 = (uint32_t)(2 * A1_H + (112 + lt) * SROW + ((lane >> 3) & 1) * 8) * 2;

    auto loadChunk = [&](int st, int ci) {
        uint32_t sa = sbase + st * STG_GRU;
        int k0 = ci * KC;
#pragma unroll
        for (int q = 0; q < 4; ++q) {           // A hi+lo: 1024 ops
            int idx = tid + 256 * q;
            int half = idx >> 9;
            int i2 = idx & 511;
            int r = i2 >> 2, sg = i2 & 3;
            cpa16(sa + (half * A1_H + r * SROW + sg * 8) * 2,
                  d_iAS + (size_t)(b0 + r) * KS + half * KP + k0 + sg * 8);
        }
#pragma unroll
        for (int q = 0; q < 2; ++q) {           // B: 120 rows x 4 = 480 ops
            int idx = tid + 256 * q;
            if (idx < 480) {
                int r = idx >> 2, sg = idx & 3;
                int s = r / JT, jt = r - s * JT;
                cpa16(sa + (2 * A1_H + r * SROW + sg * 8) * 2,
                      d_WhhS + (size_t)(s * KP + j0 + jt) * KP + k0 + sg * 8);
            }
        }
    };

    loadChunk(0, 0); CP_COMMIT();
    loadChunk(1, 1); CP_COMMIT();

#pragma unroll 1
    for (int ci = 0; ci < NCH; ++ci) {
        if (ci < NCH - 1) cp_wait<1>(); else cp_wait<0>();
        __syncthreads();
        if (ci + 2 < NCH) { loadChunk((ci + 2) % 3, ci + 2); CP_COMMIT(); }
        uint32_t stg = sbase + (ci % 3) * STG_GRU;
#pragma unroll
        for (int k16 = 0; k16 < 2; ++k16) {
            uint32_t ko2 = (uint32_t)k16 * 32;
            uint32_t ah[4], al[4];
            ldsm4(ah, stg + aoffH + ko2);
            ldsm4(al, stg + aoffL + ko2);
#pragma unroll
            for (int q = 0; q < 7; ++q) {
                uint32_t bb[4];
                ldsm4(bb, stg + boff[q] + ko2);
                mma_f16(c[2 * q],     ah, bb[0], bb[1]);
                mma_f16(c[2 * q],     al, bb[0], bb[1]);
                mma_f16(c[2 * q + 1], ah, bb[2], bb[3]);
                mma_f16(c[2 * q + 1], al, bb[2], bb[3]);
            }
            uint32_t b2[2];
            ldsm2(b2, stg + boff14 + ko2);
            mma_f16(c[14], ah, b2[0], b2[1]);
            mma_f16(c[14], al, b2[0], b2[1]);
        }
    }

    // ---- fused GRU epilogue (register-resident r/z/n; coalesced tables) ----
#pragma unroll
    for (int hf = 0; hf < 2; ++hf) {
        int row = b0 + wid * 16 + g + hf * 8;
        int t = types[row * MAXN + v], p = paths[row * MAXN + v];
        const float* t1 = d_T1 + t * 3 * KP;
        const float* t2 = d_T2 + p * 3 * KP;
#pragma unroll
        for (int nf = 0; nf < 5; ++nf) {
            int jb = j0 + nf * 8 + 2 * tig;
            float h2[2];
#pragma unroll
            for (int cl = 0; cl < 2; ++cl) {
                int j = jb + cl;
                int ci2 = hf * 2 + cl;
                float h = 0.f;
                if (j < HID) {
                    float hin = d_hin[(size_t)row * KP + j];
                    float rr = sigm(c[nf][ci2] + t1[j] + t2[j] + d_bhh3[j]);
                    float zz = sigm(c[nf + 5][ci2] + t1[KP + j] + t2[KP + j] +
                                    d_bhh3[KP + j]);
                    float nn = tanhf(t1[2 * KP + j] + t2[2 * KP + j] +
                                     rr * (c[nf + 10][ci2] + d_bhh3[2 * KP + j]));
                    h = (1.f - zz) * nn + zz * hin;
                }
                h2[cl] = h;
            }
            *(float2*)&d_hcur[(size_t)row * KP + jb] = make_float2(h2[0], h2[1]);
            __half h0h, h0l, h1h, h1l;
            hsplit(h2[0], h0h, h0l); hsplit(h2[1], h1h, h1l);
            size_t o = (size_t)row * KS + jb;
            *(__half2*)(d_hAS + o)      = __half2{h0h, h1h};
            *(__half2*)(d_hAS + o + KP) = __half2{h0l, h1l};
        }
    }
}

// ============================================================================
// Fused gate GEMM+epilogue+hin. 128 batch x 40 j x 2 mats. Unique-K loop.
// ============================================================================
__global__ void __launch_bounds__(256, 2) k_ggate(int v,
    const int* __restrict__ paths, const int* __restrict__ adj)
{
    extern __shared__ __half sm[];
    float* adjf = (float*)((char*)sm + 3 * STG_GT);   // [128][12], persists
    int tid = threadIdx.x, lane = tid & 31, wid = tid >> 5;
    int g = lane >> 2, tig = lane & 3;
    int li = lane >> 3, lt = lane & 7;
    int b0 = blockIdx.x * 128, j0 = blockIdx.y * JT;

    float c[10][4];
#pragma unroll
    for (int nf = 0; nf < 10; ++nf)
#pragma unroll
        for (int i = 0; i < 4; ++i) c[nf][i] = 0.f;

    uint32_t sbase = (uint32_t)__cvta_generic_to_shared(sm);

    uint32_t aoffH, aoffL, boff[5];
    {
        int mrow = wid * 16 + (li & 1) * 8 + lt;
        aoffH = (uint32_t)(mrow * SROW + (li >> 1) * 8) * 2;
        aoffL = aoffH + A1_H * 2;
    }
#pragma unroll
    for (int q = 0; q < 5; ++q) {
        int nrow = q * 16 + (li >> 1) * 8 + lt;
        boff[q] = (uint32_t)(2 * A1_H + nrow * SROW + (li & 1) * 8) * 2;
    }

    auto loadChunk = [&](int st, int ci) {
        uint32_t sa = sbase + st * STG_GT;
        int k0 = ci * KC;
#pragma unroll
        for (int q = 0; q < 4; ++q) {           // A hi+lo
            int idx = tid + 256 * q;
            int half = idx >> 9;
            int i2 = idx & 511;
            int r = i2 >> 2, sg = i2 & 3;
            cpa16(sa + (half * A1_H + r * SROW + sg * 8) * 2,
                  d_hAS + (size_t)(b0 + r) * KS + half * KP + k0 + sg * 8);
        }
        {                                       // B: 80 rows x 4 = 320 ops
            int idx = tid;
            int r = idx >> 2, sg = idx & 3;
            int s = r / JT, jt = r - s * JT;
            cpa16(sa + (2 * A1_H + r * SROW + sg * 8) * 2,
                  d_WgmS + (size_t)(s * KP + j0 + jt) * KP + k0 + sg * 8);
            if (tid < 64) {
                int idx2 = tid + 256;
                r = idx2 >> 2; sg = idx2 & 3;
                s = r / JT; jt = r - s * JT;
                cpa16(sa + (2 * A1_H + r * SROW + sg * 8) * 2,
                      d_WgmS + (size_t)(s * KP + j0 + jt) * KP + k0 + sg * 8);
            }
        }
    };

    loadChunk(0, 0); CP_COMMIT();
    loadChunk(1, 1); CP_COMMIT();
    for (int idx = tid; idx < 128 * MAXN; idx += 256) {
        int r = idx / MAXN, u = idx - r * MAXN;
        adjf[idx] = (float)adj[(size_t)(b0 + r) * (MAXN * MAXN) + (v + 1) * MAXN + u];
    }

#pragma unroll 1
    for (int ci = 0; ci < NCH; ++ci) {
        if (ci < NCH - 1) cp_wait<1>(); else cp_wait<0>();
        __syncthreads();
        if (ci + 2 < NCH) { loadChunk((ci + 2) % 3, ci + 2); CP_COMMIT(); }
        uint32_t stg = sbase + (ci % 3) * STG_GT;
#pragma unroll
        for (int k16 = 0; k16 < 2; ++k16) {
            uint32_t ko2 = (uint32_t)k16 * 32;
            uint32_t ah[4], al[4];
            ldsm4(ah, stg + aoffH + ko2);
            ldsm4(al, stg + aoffL + ko2);
#pragma unroll
            for (int q = 0; q < 5; ++q) {
                uint32_t bb[4];
                ldsm4(bb, stg + boff[q] + ko2);
                mma_f16(c[2 * q],     ah, bb[0], bb[1]);
                mma_f16(c[2 * q],     al, bb[0], bb[1]);
                mma_f16(c[2 * q + 1], ah, bb[2], bb[3]);
                mma_f16(c[2 * q + 1], al, bb[2], bb[3]);
            }
        }
    }

    __syncthreads();                       // stages now dead; reuse for g/hin
    float* g_s   = (float*)sm;             // [128][40]
    float* hin_s = (float*)sm + 128 * JT;  // [128][40]

    // ---- gate epilogue into smem (g/m pairs: c[nf], c[nf+5]) ----
#pragma unroll
    for (int hf = 0; hf < 2; ++hf) {
        int row = wid * 16 + g + hf * 8;
        int p = paths[(b0 + row) * MAXN + v];
        const float* tg = d_Tg + p * KP;
        const float* tm = d_Tm + p * KP;
#pragma unroll
        for (int nf = 0; nf < 5; ++nf) {
            int jl = nf * 8 + 2 * tig;
#pragma unroll
            for (int cl = 0; cl < 2; ++cl) {
                int j = j0 + jl + cl;
                int ci2 = hf * 2 + cl;
                float val = 0.f;
                if (j < HID) {
                    float gv = sigm(c[nf][ci2] + tg[j]);
                    float mv = c[nf + 5][ci2] + tm[j];
                    val = gv * mv;
                }
                g_s[row * JT + jl + cl] = val;
            }
        }
    }
    __syncthreads();

    // ---- fused hin_{v+1} for this j-slice ----
    for (int idx = tid; idx < 128 * JT; idx += 256) {
        int r = idx / JT, jj = idx - r * JT;
        float acc = 0.f;
        for (int u = 0; u < v; ++u) {
            if (adjf[r * MAXN + u] != 0.f)
                acc += d_g[((size_t)(b0 + r) * 11 + u) * KP + j0 + jj];
        }
        if (adjf[r * MAXN + v] != 0.f) acc += g_s[idx];
        hin_s[idx] = acc;
    }
    __syncthreads();

    // ---- coalesced writes: g, hin, iAS splits ----
    for (int idx = tid; idx < 128 * (JT / 4); idx += 256) {
        int r = idx / (JT / 4), sg = idx - r * (JT / 4);
        float4 g4 = *(float4*)&g_s[r * JT + sg * 4];
        *(float4*)&d_g[((size_t)(b0 + r) * 11 + v) * KP + j0 + sg * 4] = g4;
        float4 h4 = *(float4*)&hin_s[r * JT + sg * 4];
        *(float4*)&d_hin[(size_t)(b0 + r) * KP + j0 + sg * 4] = h4;
        __half h0, l0, h1, l1, h2, l2, h3, l3;
        hsplit(h4.x, h0, l0); hsplit(h4.y, h1, l1);
        hsplit(h4.z, h2, l2); hsplit(h4.w, h3, l3);
        size_t o = (size_t)(b0 + r) * KS + j0 + sg * 4;
        __half2* ph_ = (__half2*)(d_iAS + o);
        ph_[0] = __half2{h0, h1}; ph_[1] = __half2{h2, h3};
        __half2* pl_ = (__half2*)(d_iAS + o + KP);
        pl_[0] = __half2{l0, l1}; pl_[1] = __half2{l2, l3};
    }
}

// ---------------- head ------------------------------------------------------
__global__ void __launch_bounds__(128) k_head(
    const int* __restrict__ paths, const float* __restrict__ feats,
    const float* __restrict__ W_df1, const float* __restrict__ b_df1,
    const float* __restrict__ W_df2, const float* __restrict__ b_df2,
    const float* __restrict__ W_fc1, const float* __restrict__ b_fc1,
    const float* __restrict__ W_fc2, const float* __restrict__ b_fc2,
    float* __restrict__ out)
{
    int b = blockIdx.x;
    int t = threadIdx.x;
    __shared__ float hg[HID + 8];
    __shared__ float df[3 * PP];
    __shared__ float hid16[16];

    for (int j = t; j < HID; j += 128) hg[j] = d_hcur[(size_t)b * KP + j];
    if (t < 3 * PP) df[t] = 0.f;
    __syncthreads();
    if (t == 0) {
        for (int v = 0; v < MAXN; ++v) {
            int base = paths[b * MAXN + v] * 3;
            df[base]     = feats[(b * MAXN + v) * 3 + 0];
            df[base + 1] = feats[(b * MAXN + v) * 3 + 1];
            df[base + 2] = feats[(b * MAXN + v) * 3 + 2];
        }
    }
    __syncthreads();
    if (t < 16) {
        float a = b_df1[t];
        for (int k = 0; k < 3 * PP; ++k) a = fmaf(df[k], W_df1[t * (3 * PP) + k], a);
        hid16[t] = fmaxf(a, 0.f);
    }
    __syncthreads();
    if (t < 8) {
        float a = b_df2[t];
        for (int k = 0; k < 16; ++k) a = fmaf(hid16[k], W_df2[t * 16 + k], a);
        hg[HID + t] = a;
    }
    __syncthreads();
    if (t < 112) {
        const float* W;
        float a;
        int i;
        if (t < 56) { i = t;      W = W_fc1; a = b_fc1[i]; }
        else        { i = t - 56; W = W_fc2; a = b_fc2[i]; }
        const float* wrow = W + i * (HID + 8);
        for (int k = 0; k < HID + 8; ++k) a = fmaf(hg[k], wrow[k], a);
        out[b * 112 + t] = a;
    }
}

// ---------------- launcher --------------------------------------------------
extern "C" void kernel_launch(void* const* d_in, const int* in_sizes, int n_in,
                              void* d_out, int out_size)
{
    const int*   types = (const int*)d_in[0];
    const int*   paths = (const int*)d_in[1];
    const int*   adj   = (const int*)d_in[2];
    const float* feats = (const float*)d_in[3];
    const float* W_ih  = (const float*)d_in[4];
    const float* W_hh  = (const float*)d_in[5];
    const float* b_ih  = (const float*)d_in[6];
    const float* b_hh  = (const float*)d_in[7];
    const float* Wg    = (const float*)d_in[8];
    const float* bg    = (const float*)d_in[9];
    const float* Wm    = (const float*)d_in[10];
    const float* W_df1 = (const float*)d_in[11];
    const float* b_df1 = (const float*)d_in[12];
    const float* W_df2 = (const float*)d_in[13];
    const float* b_df2 = (const float*)d_in[14];
    const float* W_fc1 = (const float*)d_in[15];
    const float* b_fc1 = (const float*)d_in[16];
    const float* W_fc2 = (const float*)d_in[17];
    const float* b_fc2 = (const float*)d_in[18];
    float* out = (float*)d_out;

    cudaFuncSetAttribute(k_ggru,  cudaFuncAttributeMaxDynamicSharedMemorySize, GRU_SMEM);
    cudaFuncSetAttribute(k_ggate, cudaFuncAttributeMaxDynamicSharedMemorySize, GT_SMEM);

    dim3 grid(BB / 128, KP / JT);   // 32 x 8 = 256 blocks (single wave @ occ 2)

    const int tabN = NT * 3 * KP + PP * 3 * KP + 3 * KP + 2 * PP * KP;
    k_pad<<<(5 * HID * HID + 255) / 256, 256>>>(W_hh, Wg, Wm);
    k_tab<<<(tabN + 255) / 256, 256>>>(W_ih, b_ih, b_hh, Wg, bg, Wm);
    k_h0<<<(BB * HID + 255) / 256, 256>>>(types, paths);

    k_ggate<<<grid, 256, GT_SMEM>>>(0, paths, adj);
    for (int v = 1; v < MAXN; ++v) {
        k_ggru<<<grid, 256, GRU_SMEM>>>(v, types, paths);
        if (v < MAXN - 1)
            k_ggate<<<grid, 256, GT_SMEM>>>(v, paths, adj);
    }
    k_head<<<BB, 128>>>(paths, feats, W_df1, b_df1, W_df2, b_df2,
                        W_fc1, b_fc1, W_fc2, b_fc2, out);
}

// round 14
// speedup vs baseline: 1.5759x; 1.0105x over previous
#include <cuda_runtime.h>
#include <cuda_fp16.h>
#include <cstdint>

#define BB 4096
#define MAXN 12
#define HID 301
#define NT 10
#define PP 9
#define VSTAT 310
#define KP 320          // padded hidden (= unique K)
#define KS 640          // activation storage: [hi(320) | lo(320)] fp16
#define JT 40           // j-cols per block  -> grid 32 x 8 = 256 (single wave)
#define KC 32           // unique-K per chunk
#define NCH 10          // 320/32
#define SROW 40         // smem row stride in halves (80B; ldsm conflict-free)

#define A1_H (128 * SROW)                       // one A half-tile (halves)
#define STG_GRU ((2 * A1_H + 120 * SROW) * 2)   // 30080 B
#define STG_GT  ((2 * A1_H + 80 * SROW) * 2)    // 26880 B
#define SM_MAIN (3 * STG_GRU)                   // 90240 (gate fits: 80640+6144)

// ---------------- scratch (device globals; zero-initialized) ----------------
__device__ __align__(16) float d_g[(size_t)BB * 11 * KP];
__device__ __align__(16) float d_hcur[(size_t)BB * KP];
__device__ __align__(16) float d_hin[(size_t)BB * KP];
__device__ __align__(16) __half d_hAS[(size_t)BB * KS];
__device__ __align__(16) __half d_iAS[(size_t)BB * KS];
__device__ __align__(16) __half d_WhhS[960 * KP];   // UNIQUE K=320, rows s*320+j
__device__ __align__(16) __half d_WgmS[640 * KP];   // rows m*320+j
__device__ unsigned d_bar[32 * 24];                 // monotonic phase counters
// epilogue tables (coalesced in j)
__device__ __align__(16) float d_T1[NT * 3 * KP];   // W_ih[.,t] + b_ih
__device__ __align__(16) float d_T2[PP * 3 * KP];   // W_ih[.,NT+p]
__device__ __align__(16) float d_bhh3[3 * KP];
__device__ __align__(16) float d_Tg[PP * KP];       // Wg[.,HID+p] + bg
__device__ __align__(16) float d_Tm[PP * KP];       // Wm[.,HID+p]

__device__ __forceinline__ float sigm(float x) { return 1.f / (1.f + __expf(-x)); }
__device__ __forceinline__ void hsplit(float x, __half& hi, __half& lo) {
    hi = __float2half_rn(x);
    lo = __float2half_rn(x - __half2float(hi));
}
__device__ __forceinline__ void mma_f16(float c[4], const uint32_t a[4],
                                        uint32_t b0, uint32_t b1) {
    asm volatile(
        "mma.sync.aligned.m16n8k16.row.col.f32.f16.f16.f32 "
        "{%0,%1,%2,%3}, {%4,%5,%6,%7}, {%8,%9}, {%0,%1,%2,%3};"
        : "+f"(c[0]), "+f"(c[1]), "+f"(c[2]), "+f"(c[3])
        : "r"(a[0]), "r"(a[1]), "r"(a[2]), "r"(a[3]), "r"(b0), "r"(b1));
}
__device__ __forceinline__ void ldsm4(uint32_t* r, uint32_t addr) {
    asm volatile("ldmatrix.sync.aligned.m8n8.x4.shared.b16 {%0,%1,%2,%3}, [%4];"
                 : "=r"(r[0]), "=r"(r[1]), "=r"(r[2]), "=r"(r[3]) : "r"(addr));
}
__device__ __forceinline__ void ldsm2(uint32_t* r, uint32_t addr) {
    asm volatile("ldmatrix.sync.aligned.m8n8.x2.shared.b16 {%0,%1}, [%2];"
                 : "=r"(r[0]), "=r"(r[1]) : "r"(addr));
}
__device__ __forceinline__ void cpa16(uint32_t s, const void* g) {
    asm volatile("cp.async.ca.shared.global [%0], [%1], 16;" :: "r"(s), "l"(g));
}
#define CP_COMMIT() asm volatile("cp.async.commit_group;")
template<int N> __device__ __forceinline__ void cp_wait() {
    asm volatile("cp.async.wait_group %0;" :: "n"(N));
}

// per-batch-tile barrier among the 8 j-blocks of bx. Monotonic counters:
// each arrival epoch adds exactly 8, so target = (old & ~7) + 8 — replay-safe
// without resets. Spin backs off with __nanosleep to avoid hot atomic loops.
__device__ __forceinline__ void barx(int bx, int k) {
    __syncthreads();
    if (threadIdx.x == 0) {
        __threadfence();
        unsigned* c = &d_bar[bx * 24 + k];
        unsigned old = atomicAdd(c, 1u);
        unsigned target = (old & ~7u) + 8u;
        while (atomicAdd(c, 0u) < target) { __nanosleep(64); }
        __threadfence();
    }
    __syncthreads();
}

// ---------------- weight repack (fp16, UNIQUE K) ----------------------------
__global__ void k_pad(const float* __restrict__ Whh, const float* __restrict__ Wg,
                      const float* __restrict__ Wm)
{
    int idx = blockIdx.x * blockDim.x + threadIdx.x;
    const int total = HID * HID;
    if (idx < 3 * total) {
        int s = idx / total, r = idx - s * total, j = r / HID, k = r - j * HID;
        d_WhhS[(size_t)(s * KP + j) * KP + k] = __float2half_rn(Whh[(s * HID + j) * HID + k]);
    } else if (idx < 5 * total) {
        int m = (idx - 3 * total) / total, r = (idx - 3 * total) % total;
        int j = r / HID, k = r - j * HID;
        const float* W = m ? Wm : Wg;
        d_WgmS[(size_t)(m * KP + j) * KP + k] = __float2half_rn(W[j * VSTAT + k]);
    }
}

// ---------------- epilogue table build --------------------------------------
__global__ void k_tab(const float* __restrict__ W_ih, const float* __restrict__ b_ih,
                      const float* __restrict__ b_hh,
                      const float* __restrict__ Wg, const float* __restrict__ bg,
                      const float* __restrict__ Wm)
{
    int idx = blockIdx.x * blockDim.x + threadIdx.x;
    const int TPK = 3 * KP;
    if (idx < NT * TPK) {
        int t = idx / TPK, r = idx - t * TPK, s = r / KP, j = r - s * KP;
        d_T1[idx] = (j < HID) ? W_ih[(size_t)(s * HID + j) * 19 + t] + b_ih[s * HID + j] : 0.f;
    } else if (idx < NT * TPK + PP * TPK) {
        int q = idx - NT * TPK;
        int p = q / TPK, r = q - p * TPK, s = r / KP, j = r - s * KP;
        d_T2[q] = (j < HID) ? W_ih[(size_t)(s * HID + j) * 19 + NT + p] : 0.f;
    } else if (idx < NT * TPK + PP * TPK + TPK) {
        int q = idx - NT * TPK - PP * TPK;
        int s = q / KP, j = q - s * KP;
        d_bhh3[q] = (j < HID) ? b_hh[s * HID + j] : 0.f;
    } else if (idx < NT * TPK + PP * TPK + TPK + PP * KP) {
        int q = idx - NT * TPK - PP * TPK - TPK;
        int p = q / KP, j = q - p * KP;
        d_Tg[q] = (j < HID) ? Wg[(size_t)j * VSTAT + HID + p] + bg[j] : 0.f;
    } else if (idx < NT * TPK + PP * TPK + TPK + 2 * PP * KP) {
        int q = idx - NT * TPK - PP * TPK - TPK - PP * KP;
        int p = q / KP, j = q - p * KP;
        d_Tm[q] = (j < HID) ? Wm[(size_t)j * VSTAT + HID + p] : 0.f;
    }
}

// ============================================================================
// Persistent recurrence kernel: h0 + 12 GRU steps + 11 gate steps,
// per-batch-tile barriers (8 blocks). Grid 32 x 8, occ 2 => all co-resident.
// ============================================================================
__global__ void __launch_bounds__(256, 2) k_main(
    const int* __restrict__ types, const int* __restrict__ paths,
    const int* __restrict__ adj)
{
    extern __shared__ __half sm[];
    int tid = threadIdx.x, lane = tid & 31, wid = tid >> 5;
    int g = lane >> 2, tig = lane & 3;
    int li = lane >> 3, lt = lane & 7;
    int bx = blockIdx.x, jy = blockIdx.y;
    int b0 = bx * 128, j0 = jy * JT;

    uint32_t sbase = (uint32_t)__cvta_generic_to_shared(sm);

    // fragment smem offsets
    uint32_t aoffH, aoffL, bfG[7], bfG14, bfT[5];
    {
        int mrow = wid * 16 + (li & 1) * 8 + lt;
        aoffH = (uint32_t)(mrow * SROW + (li >> 1) * 8) * 2;
        aoffL = aoffH + A1_H * 2;
    }
#pragma unroll
    for (int q = 0; q < 7; ++q) {
        int nrow = q * 16 + (li >> 1) * 8 + lt;
        bfG[q] = (uint32_t)(2 * A1_H + nrow * SROW + (li & 1) * 8) * 2;
    }
    bfG14 = (uint32_t)(2 * A1_H + (112 + lt) * SROW + ((lane >> 3) & 1) * 8) * 2;
#pragma unroll
    for (int q = 0; q < 5; ++q) {
        int nrow = q * 16 + (li >> 1) * 8 + lt;
        bfT[q] = (uint32_t)(2 * A1_H + nrow * SROW + (li & 1) * 8) * 2;
    }

    // ---------------- phase: h0 (this block's 128 x 40 slab) ----------------
    for (int idx = tid; idx < 128 * JT; idx += 256) {
        int r = idx / JT, jj = idx - r * JT;
        int j = j0 + jj;
        if (j >= HID) continue;
        int b = b0 + r;
        int t = types[b * MAXN], p = paths[b * MAXN];
        const float* t1 = d_T1 + t * 3 * KP;
        const float* t2 = d_T2 + p * 3 * KP;
        float rr = sigm(t1[j] + t2[j] + d_bhh3[j]);
        float zz = sigm(t1[KP + j] + t2[KP + j] + d_bhh3[KP + j]);
        float nn = tanhf(t1[2 * KP + j] + t2[2 * KP + j] + rr * d_bhh3[2 * KP + j]);
        float h = (1.f - zz) * nn;
        d_hcur[(size_t)b * KP + j] = h;
        __half hi, lo; hsplit(h, hi, lo);
        size_t o = (size_t)b * KS + j;
        d_hAS[o] = hi; d_hAS[o + KP] = lo;
    }
    barx(bx, 0);

    for (int v = 0; v < 11; ++v) {
        // ================= gate(v) phase =================
        {
            float* adjf = (float*)((char*)sm + 3 * STG_GT);   // [128][12]
            float c[10][4];
#pragma unroll
            for (int nf = 0; nf < 10; ++nf)
#pragma unroll
                for (int i = 0; i < 4; ++i) c[nf][i] = 0.f;

            auto loadChunk = [&](int st, int ci) {
                uint32_t sa = sbase + st * STG_GT;
                int k0 = ci * KC;
#pragma unroll
                for (int q = 0; q < 4; ++q) {
                    int idx = tid + 256 * q;
                    int half = idx >> 9;
                    int i2 = idx & 511;
                    int r = i2 >> 2, sg = i2 & 3;
                    cpa16(sa + (half * A1_H + r * SROW + sg * 8) * 2,
                          d_hAS + (size_t)(b0 + r) * KS + half * KP + k0 + sg * 8);
                }
                {
                    int r = tid >> 2, sg = tid & 3;
                    int s = r / JT, jt = r - s * JT;
                    cpa16(sa + (2 * A1_H + r * SROW + sg * 8) * 2,
                          d_WgmS + (size_t)(s * KP + j0 + jt) * KP + k0 + sg * 8);
                    if (tid < 64) {
                        int idx2 = tid + 256;
                        r = idx2 >> 2; sg = idx2 & 3;
                        s = r / JT; jt = r - s * JT;
                        cpa16(sa + (2 * A1_H + r * SROW + sg * 8) * 2,
                              d_WgmS + (size_t)(s * KP + j0 + jt) * KP + k0 + sg * 8);
                    }
                }
            };

            loadChunk(0, 0); CP_COMMIT();
            loadChunk(1, 1); CP_COMMIT();
            for (int idx = tid; idx < 128 * MAXN; idx += 256) {
                int r = idx / MAXN, u = idx - r * MAXN;
                adjf[idx] = (float)adj[(size_t)(b0 + r) * (MAXN * MAXN) + (v + 1) * MAXN + u];
            }

#pragma unroll 1
            for (int ci = 0; ci < NCH; ++ci) {
                if (ci < NCH - 1) cp_wait<1>(); else cp_wait<0>();
                __syncthreads();
                if (ci + 2 < NCH) { loadChunk((ci + 2) % 3, ci + 2); CP_COMMIT(); }
                uint32_t stg = sbase + (ci % 3) * STG_GT;
#pragma unroll
                for (int k16 = 0; k16 < 2; ++k16) {
                    uint32_t ko2 = (uint32_t)k16 * 32;
                    uint32_t ah[4], al[4];
                    ldsm4(ah, stg + aoffH + ko2);
                    ldsm4(al, stg + aoffL + ko2);
#pragma unroll
                    for (int q = 0; q < 5; ++q) {
                        uint32_t bb[4];
                        ldsm4(bb, stg + bfT[q] + ko2);
                        mma_f16(c[2 * q],     ah, bb[0], bb[1]);
                        mma_f16(c[2 * q],     al, bb[0], bb[1]);
                        mma_f16(c[2 * q + 1], ah, bb[2], bb[3]);
                        mma_f16(c[2 * q + 1], al, bb[2], bb[3]);
                    }
                }
            }

            __syncthreads();
            float* g_s   = (float*)sm;             // [128][40]
            float* hin_s = (float*)sm + 128 * JT;  // [128][40]

#pragma unroll
            for (int hf = 0; hf < 2; ++hf) {
                int row = wid * 16 + g + hf * 8;
                int p = paths[(b0 + row) * MAXN + v];
                const float* tg = d_Tg + p * KP;
                const float* tm = d_Tm + p * KP;
#pragma unroll
                for (int nf = 0; nf < 5; ++nf) {
                    int jl = nf * 8 + 2 * tig;
#pragma unroll
                    for (int cl = 0; cl < 2; ++cl) {
                        int j = j0 + jl + cl;
                        int ci2 = hf * 2 + cl;
                        float val = 0.f;
                        if (j < HID) {
                            float gv = sigm(c[nf][ci2] + tg[j]);
                            float mv = c[nf + 5][ci2] + tm[j];
                            val = gv * mv;
                        }
                        g_s[row * JT + jl + cl] = val;
                    }
                }
            }
            __syncthreads();

            for (int idx = tid; idx < 128 * JT; idx += 256) {
                int r = idx / JT, jj = idx - r * JT;
                float acc = 0.f;
                for (int u = 0; u < v; ++u) {
                    if (adjf[r * MAXN + u] != 0.f)
                        acc += d_g[((size_t)(b0 + r) * 11 + u) * KP + j0 + jj];
                }
                if (adjf[r * MAXN + v] != 0.f) acc += g_s[idx];
                hin_s[idx] = acc;
            }
            __syncthreads();

            for (int idx = tid; idx < 128 * (JT / 4); idx += 256) {
                int r = idx / (JT / 4), sg = idx - r * (JT / 4);
                float4 g4 = *(float4*)&g_s[r * JT + sg * 4];
                *(float4*)&d_g[((size_t)(b0 + r) * 11 + v) * KP + j0 + sg * 4] = g4;
                float4 h4 = *(float4*)&hin_s[r * JT + sg * 4];
                *(float4*)&d_hin[(size_t)(b0 + r) * KP + j0 + sg * 4] = h4;
                __half h0, l0, h1, l1, h2, l2, h3, l3;
                hsplit(h4.x, h0, l0); hsplit(h4.y, h1, l1);
                hsplit(h4.z, h2, l2); hsplit(h4.w, h3, l3);
                size_t o = (size_t)(b0 + r) * KS + j0 + sg * 4;
                __half2* ph_ = (__half2*)(d_iAS + o);
                ph_[0] = __half2{h0, h1}; ph_[1] = __half2{h2, h3};
                __half2* pl_ = (__half2*)(d_iAS + o + KP);
                pl_[0] = __half2{l0, l1}; pl_[1] = __half2{l2, l3};
            }
        }
        barx(bx, 1 + 2 * v);

        // ================= gru(v+1) phase =================
        {
            int vv = v + 1;
            float c[15][4];
#pragma unroll
            for (int nf = 0; nf < 15; ++nf)
#pragma unroll
                for (int i = 0; i < 4; ++i) c[nf][i] = 0.f;

            auto loadChunk = [&](int st, int ci) {
                uint32_t sa = sbase + st * STG_GRU;
                int k0 = ci * KC;
#pragma unroll
                for (int q = 0; q < 4; ++q) {
                    int idx = tid + 256 * q;
                    int half = idx >> 9;
                    int i2 = idx & 511;
                    int r = i2 >> 2, sg = i2 & 3;
                    cpa16(sa + (half * A1_H + r * SROW + sg * 8) * 2,
                          d_iAS + (size_t)(b0 + r) * KS + half * KP + k0 + sg * 8);
                }
#pragma unroll
                for (int q = 0; q < 2; ++q) {
                    int idx = tid + 256 * q;
                    if (idx < 480) {
                        int r = idx >> 2, sg = idx & 3;
                        int s = r / JT, jt = r - s * JT;
                        cpa16(sa + (2 * A1_H + r * SROW + sg * 8) * 2,
                              d_WhhS + (size_t)(s * KP + j0 + jt) * KP + k0 + sg * 8);
                    }
                }
            };

            loadChunk(0, 0); CP_COMMIT();
            loadChunk(1, 1); CP_COMMIT();

#pragma unroll 1
            for (int ci = 0; ci < NCH; ++ci) {
                if (ci < NCH - 1) cp_wait<1>(); else cp_wait<0>();
                __syncthreads();
                if (ci + 2 < NCH) { loadChunk((ci + 2) % 3, ci + 2); CP_COMMIT(); }
                uint32_t stg = sbase + (ci % 3) * STG_GRU;
#pragma unroll
                for (int k16 = 0; k16 < 2; ++k16) {
                    uint32_t ko2 = (uint32_t)k16 * 32;
                    uint32_t ah[4], al[4];
                    ldsm4(ah, stg + aoffH + ko2);
                    ldsm4(al, stg + aoffL + ko2);
#pragma unroll
                    for (int q = 0; q < 7; ++q) {
                        uint32_t bb[4];
                        ldsm4(bb, stg + bfG[q] + ko2);
                        mma_f16(c[2 * q],     ah, bb[0], bb[1]);
                        mma_f16(c[2 * q],     al, bb[0], bb[1]);
                        mma_f16(c[2 * q + 1], ah, bb[2], bb[3]);
                        mma_f16(c[2 * q + 1], al, bb[2], bb[3]);
                    }
                    uint32_t b2[2];
                    ldsm2(b2, stg + bfG14 + ko2);
                    mma_f16(c[14], ah, b2[0], b2[1]);
                    mma_f16(c[14], al, b2[0], b2[1]);
                }
            }

#pragma unroll
            for (int hf = 0; hf < 2; ++hf) {
                int row = b0 + wid * 16 + g + hf * 8;
                int t = types[row * MAXN + vv], p = paths[row * MAXN + vv];
                const float* t1 = d_T1 + t * 3 * KP;
                const float* t2 = d_T2 + p * 3 * KP;
#pragma unroll
                for (int nf = 0; nf < 5; ++nf) {
                    int jb = j0 + nf * 8 + 2 * tig;
                    float h2[2];
#pragma unroll
                    for (int cl = 0; cl < 2; ++cl) {
                        int j = jb + cl;
                        int ci2 = hf * 2 + cl;
                        float h = 0.f;
                        if (j < HID) {
                            float hin = d_hin[(size_t)row * KP + j];
                            float rr = sigm(c[nf][ci2] + t1[j] + t2[j] + d_bhh3[j]);
                            float zz = sigm(c[nf + 5][ci2] + t1[KP + j] + t2[KP + j] +
                                            d_bhh3[KP + j]);
                            float nn = tanhf(t1[2 * KP + j] + t2[2 * KP + j] +
                                             rr * (c[nf + 10][ci2] + d_bhh3[2 * KP + j]));
                            h = (1.f - zz) * nn + zz * hin;
                        }
                        h2[cl] = h;
                    }
                    *(float2*)&d_hcur[(size_t)row * KP + jb] = make_float2(h2[0], h2[1]);
                    __half h0h, h0l, h1h, h1l;
                    hsplit(h2[0], h0h, h0l); hsplit(h2[1], h1h, h1l);
                    size_t o = (size_t)row * KS + jb;
                    *(__half2*)(d_hAS + o)      = __half2{h0h, h1h};
                    *(__half2*)(d_hAS + o + KP) = __half2{h0l, h1l};
                }
            }
        }
        if (v < 10) barx(bx, 2 + 2 * v);
    }
}

// ---------------- head ------------------------------------------------------
__global__ void __launch_bounds__(128) k_head(
    const int* __restrict__ paths, const float* __restrict__ feats,
    const float* __restrict__ W_df1, const float* __restrict__ b_df1,
    const float* __restrict__ W_df2, const float* __restrict__ b_df2,
    const float* __restrict__ W_fc1, const float* __restrict__ b_fc1,
    const float* __restrict__ W_fc2, const float* __restrict__ b_fc2,
    float* __restrict__ out)
{
    int b = blockIdx.x;
    int t = threadIdx.x;
    __shared__ float hg[HID + 8];
    __shared__ float df[3 * PP];
    __shared__ float hid16[16];

    for (int j = t; j < HID; j += 128) hg[j] = d_hcur[(size_t)b * KP + j];
    if (t < 3 * PP) df[t] = 0.f;
    __syncthreads();
    if (t == 0) {
        for (int v = 0; v < MAXN; ++v) {
            int base = paths[b * MAXN + v] * 3;
            df[base]     = feats[(b * MAXN + v) * 3 + 0];
            df[base + 1] = feats[(b * MAXN + v) * 3 + 1];
            df[base + 2] = feats[(b * MAXN + v) * 3 + 2];
        }
    }
    __syncthreads();
    if (t < 16) {
        float a = b_df1[t];
        for (int k = 0; k < 3 * PP; ++k) a = fmaf(df[k], W_df1[t * (3 * PP) + k], a);
        hid16[t] = fmaxf(a, 0.f);
    }
    __syncthreads();
    if (t < 8) {
        float a = b_df2[t];
        for (int k = 0; k < 16; ++k) a = fmaf(hid16[k], W_df2[t * 16 + k], a);
        hg[HID + t] = a;
    }
    __syncthreads();
    if (t < 112) {
        const float* W;
        float a;
        int i;
        if (t < 56) { i = t;      W = W_fc1; a = b_fc1[i]; }
        else        { i = t - 56; W = W_fc2; a = b_fc2[i]; }
        const float* wrow = W + i * (HID + 8);
        for (int k = 0; k < HID + 8; ++k) a = fmaf(hg[k], wrow[k], a);
        out[b * 112 + t] = a;
    }
}

// ---------------- launcher --------------------------------------------------
extern "C" void kernel_launch(void* const* d_in, const int* in_sizes, int n_in,
                              void* d_out, int out_size)
{
    const int*   types = (const int*)d_in[0];
    const int*   paths = (const int*)d_in[1];
    const int*   adj   = (const int*)d_in[2];
    const float* feats = (const float*)d_in[3];
    const float* W_ih  = (const float*)d_in[4];
    const float* W_hh  = (const float*)d_in[5];
    const float* b_ih  = (const float*)d_in[6];
    const float* b_hh  = (const float*)d_in[7];
    const float* Wg    = (const float*)d_in[8];
    const float* bg    = (const float*)d_in[9];
    const float* Wm    = (const float*)d_in[10];
    const float* W_df1 = (const float*)d_in[11];
    const float* b_df1 = (const float*)d_in[12];
    const float* W_df2 = (const float*)d_in[13];
    const float* b_df2 = (const float*)d_in[14];
    const float* W_fc1 = (const float*)d_in[15];
    const float* b_fc1 = (const float*)d_in[16];
    const float* W_fc2 = (const float*)d_in[17];
    const float* b_fc2 = (const float*)d_in[18];
    float* out = (float*)d_out;

    cudaFuncSetAttribute(k_main, cudaFuncAttributeMaxDynamicSharedMemorySize, SM_MAIN);

    const int tabN = NT * 3 * KP + PP * 3 * KP + 3 * KP + 2 * PP * KP;
    k_pad<<<(5 * HID * HID + 255) / 256, 256>>>(W_hh, Wg, Wm);
    k_tab<<<(tabN + 255) / 256, 256>>>(W_ih, b_ih, b_hh, Wg, bg, Wm);

    dim3 grid(32, 8);   // 256 blocks < 296 capacity -> all co-resident
    k_main<<<grid, 256, SM_MAIN>>>(types, paths, adj);

    k_head<<<BB, 128>>>(paths, feats, W_df1, b_df1, W_df2, b_df2,
                        W_fc1, b_fc1, W_fc2, b_fc2, out);
}

// round 15
// speedup vs baseline: 1.8575x; 1.1787x over previous
#include <cuda_runtime.h>
#include <cuda_fp16.h>
#include <cstdint>

#define BB 4096
#define MAXN 12
#define HID 301
#define NT 10
#define PP 9
#define VSTAT 310
#define KP 320          // padded hidden (= unique K)
#define KS 640          // activation storage: [hi(320) | lo(320)] fp16
#define JT 40           // j-cols per block  -> grid 32 x 8 = 256 (single wave)
#define KC 32           // unique-K per chunk
#define NCH 10          // 320/32
#define SROW 40         // smem row stride in halves (80B; ldsm conflict-free)

#define A1_H (128 * SROW)                       // one A half-tile (halves)
#define STG_GRU ((2 * A1_H + 120 * SROW) * 2)   // 30080 B
#define STG_GT  ((2 * A1_H + 80 * SROW) * 2)    // 26880 B
#define SM_MAIN (3 * STG_GRU)                   // 90240 (gate fits: 80640+6144)

// ---------------- scratch (device globals; zero-initialized) ----------------
__device__ __align__(16) float d_g[(size_t)BB * 11 * KP];
__device__ __align__(16) float d_hcur[(size_t)BB * KP];
__device__ __align__(16) float d_hin[(size_t)BB * KP];
__device__ __align__(16) __half d_hAS[(size_t)BB * KS];
__device__ __align__(16) __half d_iAS[(size_t)BB * KS];
__device__ __align__(16) __half d_WhhS[960 * KP];   // UNIQUE K=320, rows s*320+j
__device__ __align__(16) __half d_WgmS[640 * KP];   // rows m*320+j
__device__ unsigned d_bar[32 * 24];                 // monotonic phase counters
// epilogue tables (coalesced in j)
__device__ __align__(16) float d_T1[NT * 3 * KP];   // W_ih[.,t] + b_ih
__device__ __align__(16) float d_T2[PP * 3 * KP];   // W_ih[.,NT+p]
__device__ __align__(16) float d_bhh3[3 * KP];
__device__ __align__(16) float d_Tg[PP * KP];       // Wg[.,HID+p] + bg
__device__ __align__(16) float d_Tm[PP * KP];       // Wm[.,HID+p]
// head GEMM weights: rows 0..55 = fc1, 56..111 = fc2, K padded to 320
__device__ __align__(16) float d_Wfc[128 * KP];
__device__ __align__(16) float d_bfc[128];

__device__ __forceinline__ float sigm(float x) { return 1.f / (1.f + __expf(-x)); }
__device__ __forceinline__ void hsplit(float x, __half& hi, __half& lo) {
    hi = __float2half_rn(x);
    lo = __float2half_rn(x - __half2float(hi));
}
__device__ __forceinline__ void mma_f16(float c[4], const uint32_t a[4],
                                        uint32_t b0, uint32_t b1) {
    asm volatile(
        "mma.sync.aligned.m16n8k16.row.col.f32.f16.f16.f32 "
        "{%0,%1,%2,%3}, {%4,%5,%6,%7}, {%8,%9}, {%0,%1,%2,%3};"
        : "+f"(c[0]), "+f"(c[1]), "+f"(c[2]), "+f"(c[3])
        : "r"(a[0]), "r"(a[1]), "r"(a[2]), "r"(a[3]), "r"(b0), "r"(b1));
}
__device__ __forceinline__ void ldsm4(uint32_t* r, uint32_t addr) {
    asm volatile("ldmatrix.sync.aligned.m8n8.x4.shared.b16 {%0,%1,%2,%3}, [%4];"
                 : "=r"(r[0]), "=r"(r[1]), "=r"(r[2]), "=r"(r[3]) : "r"(addr));
}
__device__ __forceinline__ void ldsm2(uint32_t* r, uint32_t addr) {
    asm volatile("ldmatrix.sync.aligned.m8n8.x2.shared.b16 {%0,%1}, [%2];"
                 : "=r"(r[0]), "=r"(r[1]) : "r"(addr));
}
__device__ __forceinline__ void cpa16(uint32_t s, const void* g) {
    asm volatile("cp.async.ca.shared.global [%0], [%1], 16;" :: "r"(s), "l"(g));
}
#define CP_COMMIT() asm volatile("cp.async.commit_group;")
template<int N> __device__ __forceinline__ void cp_wait() {
    asm volatile("cp.async.wait_group %0;" :: "n"(N));
}

// per-batch-tile barrier among the 8 j-blocks of bx. Monotonic counters:
// each arrival epoch adds exactly 8, so target = (old & ~7) + 8 — replay-safe.
__device__ __forceinline__ void barx(int bx, int k) {
    __syncthreads();
    if (threadIdx.x == 0) {
        __threadfence();
        unsigned* c = &d_bar[bx * 24 + k];
        unsigned old = atomicAdd(c, 1u);
        unsigned target = (old & ~7u) + 8u;
        while (atomicAdd(c, 0u) < target) { __nanosleep(64); }
        __threadfence();
    }
    __syncthreads();
}

// ---------------- weight repack (fp16, UNIQUE K) ----------------------------
__global__ void k_pad(const float* __restrict__ Whh, const float* __restrict__ Wg,
                      const float* __restrict__ Wm)
{
    int idx = blockIdx.x * blockDim.x + threadIdx.x;
    const int total = HID * HID;
    if (idx < 3 * total) {
        int s = idx / total, r = idx - s * total, j = r / HID, k = r - j * HID;
        d_WhhS[(size_t)(s * KP + j) * KP + k] = __float2half_rn(Whh[(s * HID + j) * HID + k]);
    } else if (idx < 5 * total) {
        int m = (idx - 3 * total) / total, r = (idx - 3 * total) % total;
        int j = r / HID, k = r - j * HID;
        const float* W = m ? Wm : Wg;
        d_WgmS[(size_t)(m * KP + j) * KP + k] = __float2half_rn(W[j * VSTAT + k]);
    }
}

// ---------------- epilogue table build --------------------------------------
__global__ void k_tab(const float* __restrict__ W_ih, const float* __restrict__ b_ih,
                      const float* __restrict__ b_hh,
                      const float* __restrict__ Wg, const float* __restrict__ bg,
                      const float* __restrict__ Wm)
{
    int idx = blockIdx.x * blockDim.x + threadIdx.x;
    const int TPK = 3 * KP;
    if (idx < NT * TPK) {
        int t = idx / TPK, r = idx - t * TPK, s = r / KP, j = r - s * KP;
        d_T1[idx] = (j < HID) ? W_ih[(size_t)(s * HID + j) * 19 + t] + b_ih[s * HID + j] : 0.f;
    } else if (idx < NT * TPK + PP * TPK) {
        int q = idx - NT * TPK;
        int p = q / TPK, r = q - p * TPK, s = r / KP, j = r - s * KP;
        d_T2[q] = (j < HID) ? W_ih[(size_t)(s * HID + j) * 19 + NT + p] : 0.f;
    } else if (idx < NT * TPK + PP * TPK + TPK) {
        int q = idx - NT * TPK - PP * TPK;
        int s = q / KP, j = q - s * KP;
        d_bhh3[q] = (j < HID) ? b_hh[s * HID + j] : 0.f;
    } else if (idx < NT * TPK + PP * TPK + TPK + PP * KP) {
        int q = idx - NT * TPK - PP * TPK - TPK;
        int p = q / KP, j = q - p * KP;
        d_Tg[q] = (j < HID) ? Wg[(size_t)j * VSTAT + HID + p] + bg[j] : 0.f;
    } else if (idx < NT * TPK + PP * TPK + TPK + 2 * PP * KP) {
        int q = idx - NT * TPK - PP * TPK - TPK - PP * KP;
        int p = q / KP, j = q - p * KP;
        d_Tm[q] = (j < HID) ? Wm[(size_t)j * VSTAT + HID + p] : 0.f;
    }
}

// ---------------- head weight pad build -------------------------------------
__global__ void k_wfc(const float* __restrict__ W_fc1, const float* __restrict__ b_fc1,
                      const float* __restrict__ W_fc2, const float* __restrict__ b_fc2)
{
    int idx = blockIdx.x * blockDim.x + threadIdx.x;
    if (idx < 112 * KP) {
        int o = idx / KP, k = idx - o * KP;
        float v = 0.f;
        if (k < HID + 8)
            v = (o < 56) ? W_fc1[o * (HID + 8) + k] : W_fc2[(o - 56) * (HID + 8) + k];
        d_Wfc[o * KP + k] = v;
    } else if (idx < 112 * KP + 112) {
        int o = idx - 112 * KP;
        d_bfc[o] = (o < 56) ? b_fc1[o] : b_fc2[o - 56];
    }
}

// ============================================================================
// Persistent recurrence kernel: h0 + 12 GRU steps + 11 gate steps,
// per-batch-tile barriers (8 blocks). Grid 32 x 8, occ 2 => all co-resident.
// ============================================================================
__global__ void __launch_bounds__(256, 2) k_main(
    const int* __restrict__ types, const int* __restrict__ paths,
    const int* __restrict__ adj)
{
    extern __shared__ __half sm[];
    int tid = threadIdx.x, lane = tid & 31, wid = tid >> 5;
    int g = lane >> 2, tig = lane & 3;
    int li = lane >> 3, lt = lane & 7;
    int bx = blockIdx.x, jy = blockIdx.y;
    int b0 = bx * 128, j0 = jy * JT;

    uint32_t sbase = (uint32_t)__cvta_generic_to_shared(sm);

    // fragment smem offsets
    uint32_t aoffH, aoffL, bfG[7], bfG14, bfT[5];
    {
        int mrow = wid * 16 + (li & 1) * 8 + lt;
        aoffH = (uint32_t)(mrow * SROW + (li >> 1) * 8) * 2;
        aoffL = aoffH + A1_H * 2;
    }
#pragma unroll
    for (int q = 0; q < 7; ++q) {
        int nrow = q * 16 + (li >> 1) * 8 + lt;
        bfG[q] = (uint32_t)(2 * A1_H + nrow * SROW + (li & 1) * 8) * 2;
    }
    bfG14 = (uint32_t)(2 * A1_H + (112 + lt) * SROW + ((lane >> 3) & 1) * 8) * 2;
#pragma unroll
    for (int q = 0; q < 5; ++q) {
        int nrow = q * 16 + (li >> 1) * 8 + lt;
        bfT[q] = (uint32_t)(2 * A1_H + nrow * SROW + (li & 1) * 8) * 2;
    }

    // ---------------- phase: h0 (this block's 128 x 40 slab) ----------------
    for (int idx = tid; idx < 128 * JT; idx += 256) {
        int r = idx / JT, jj = idx - r * JT;
        int j = j0 + jj;
        if (j >= HID) continue;
        int b = b0 + r;
        int t = types[b * MAXN], p = paths[b * MAXN];
        const float* t1 = d_T1 + t * 3 * KP;
        const float* t2 = d_T2 + p * 3 * KP;
        float rr = sigm(t1[j] + t2[j] + d_bhh3[j]);
        float zz = sigm(t1[KP + j] + t2[KP + j] + d_bhh3[KP + j]);
        float nn = tanhf(t1[2 * KP + j] + t2[2 * KP + j] + rr * d_bhh3[2 * KP + j]);
        float h = (1.f - zz) * nn;
        d_hcur[(size_t)b * KP + j] = h;
        __half hi, lo; hsplit(h, hi, lo);
        size_t o = (size_t)b * KS + j;
        d_hAS[o] = hi; d_hAS[o + KP] = lo;
    }
    barx(bx, 0);

    for (int v = 0; v < 11; ++v) {
        // ================= gate(v) phase =================
        {
            float* adjf = (float*)((char*)sm + 3 * STG_GT);   // [128][12]
            float c[10][4];
#pragma unroll
            for (int nf = 0; nf < 10; ++nf)
#pragma unroll
                for (int i = 0; i < 4; ++i) c[nf][i] = 0.f;

            auto loadChunk = [&](int st, int ci) {
                uint32_t sa = sbase + st * STG_GT;
                int k0 = ci * KC;
#pragma unroll
                for (int q = 0; q < 4; ++q) {
                    int idx = tid + 256 * q;
                    int half = idx >> 9;
                    int i2 = idx & 511;
                    int r = i2 >> 2, sg = i2 & 3;
                    cpa16(sa + (half * A1_H + r * SROW + sg * 8) * 2,
                          d_hAS + (size_t)(b0 + r) * KS + half * KP + k0 + sg * 8);
                }
                {
                    int r = tid >> 2, sg = tid & 3;
                    int s = r / JT, jt = r - s * JT;
                    cpa16(sa + (2 * A1_H + r * SROW + sg * 8) * 2,
                          d_WgmS + (size_t)(s * KP + j0 + jt) * KP + k0 + sg * 8);
                    if (tid < 64) {
                        int idx2 = tid + 256;
                        r = idx2 >> 2; sg = idx2 & 3;
                        s = r / JT; jt = r - s * JT;
                        cpa16(sa + (2 * A1_H + r * SROW + sg * 8) * 2,
                              d_WgmS + (size_t)(s * KP + j0 + jt) * KP + k0 + sg * 8);
                    }
                }
            };

            loadChunk(0, 0); CP_COMMIT();
            loadChunk(1, 1); CP_COMMIT();
            for (int idx = tid; idx < 128 * MAXN; idx += 256) {
                int r = idx / MAXN, u = idx - r * MAXN;
                adjf[idx] = (float)adj[(size_t)(b0 + r) * (MAXN * MAXN) + (v + 1) * MAXN + u];
            }

#pragma unroll 1
            for (int ci = 0; ci < NCH; ++ci) {
                if (ci < NCH - 1) cp_wait<1>(); else cp_wait<0>();
                __syncthreads();
                if (ci + 2 < NCH) { loadChunk((ci + 2) % 3, ci + 2); CP_COMMIT(); }
                uint32_t stg = sbase + (ci % 3) * STG_GT;
#pragma unroll
                for (int k16 = 0; k16 < 2; ++k16) {
                    uint32_t ko2 = (uint32_t)k16 * 32;
                    uint32_t ah[4], al[4];
                    ldsm4(ah, stg + aoffH + ko2);
                    ldsm4(al, stg + aoffL + ko2);
#pragma unroll
                    for (int q = 0; q < 5; ++q) {
                        uint32_t bb[4];
                        ldsm4(bb, stg + bfT[q] + ko2);
                        mma_f16(c[2 * q],     ah, bb[0], bb[1]);
                        mma_f16(c[2 * q],     al, bb[0], bb[1]);
                        mma_f16(c[2 * q + 1], ah, bb[2], bb[3]);
                        mma_f16(c[2 * q + 1], al, bb[2], bb[3]);
                    }
                }
            }

            __syncthreads();
            float* g_s   = (float*)sm;             // [128][40]
            float* hin_s = (float*)sm + 128 * JT;  // [128][40]

#pragma unroll
            for (int hf = 0; hf < 2; ++hf) {
                int row = wid * 16 + g + hf * 8;
                int p = paths[(b0 + row) * MAXN + v];
                const float* tg = d_Tg + p * KP;
                const float* tm = d_Tm + p * KP;
#pragma unroll
                for (int nf = 0; nf < 5; ++nf) {
                    int jl = nf * 8 + 2 * tig;
#pragma unroll
                    for (int cl = 0; cl < 2; ++cl) {
                        int j = j0 + jl + cl;
                        int ci2 = hf * 2 + cl;
                        float val = 0.f;
                        if (j < HID) {
                            float gv = sigm(c[nf][ci2] + tg[j]);
                            float mv = c[nf + 5][ci2] + tm[j];
                            val = gv * mv;
                        }
                        g_s[row * JT + jl + cl] = val;
                    }
                }
            }
            __syncthreads();

            for (int idx = tid; idx < 128 * JT; idx += 256) {
                int r = idx / JT, jj = idx - r * JT;
                float acc = 0.f;
                for (int u = 0; u < v; ++u) {
                    if (adjf[r * MAXN + u] != 0.f)
                        acc += d_g[((size_t)(b0 + r) * 11 + u) * KP + j0 + jj];
                }
                if (adjf[r * MAXN + v] != 0.f) acc += g_s[idx];
                hin_s[idx] = acc;
            }
            __syncthreads();

            for (int idx = tid; idx < 128 * (JT / 4); idx += 256) {
                int r = idx / (JT / 4), sg = idx - r * (JT / 4);
                float4 g4 = *(float4*)&g_s[r * JT + sg * 4];
                *(float4*)&d_g[((size_t)(b0 + r) * 11 + v) * KP + j0 + sg * 4] = g4;
                float4 h4 = *(float4*)&hin_s[r * JT + sg * 4];
                *(float4*)&d_hin[(size_t)(b0 + r) * KP + j0 + sg * 4] = h4;
                __half h0, l0, h1, l1, h2, l2, h3, l3;
                hsplit(h4.x, h0, l0); hsplit(h4.y, h1, l1);
                hsplit(h4.z, h2, l2); hsplit(h4.w, h3, l3);
                size_t o = (size_t)(b0 + r) * KS + j0 + sg * 4;
                __half2* ph_ = (__half2*)(d_iAS + o);
                ph_[0] = __half2{h0, h1}; ph_[1] = __half2{h2, h3};
                __half2* pl_ = (__half2*)(d_iAS + o + KP);
                pl_[0] = __half2{l0, l1}; pl_[1] = __half2{l2, l3};
            }
        }
        barx(bx, 1 + 2 * v);

        // ================= gru(v+1) phase =================
        {
            int vv = v + 1;
            float c[15][4];
#pragma unroll
            for (int nf = 0; nf < 15; ++nf)
#pragma unroll
                for (int i = 0; i < 4; ++i) c[nf][i] = 0.f;

            auto loadChunk = [&](int st, int ci) {
                uint32_t sa = sbase + st * STG_GRU;
                int k0 = ci * KC;
#pragma unroll
                for (int q = 0; q < 4; ++q) {
                    int idx = tid + 256 * q;
                    int half = idx >> 9;
                    int i2 = idx & 511;
                    int r = i2 >> 2, sg = i2 & 3;
                    cpa16(sa + (half * A1_H + r * SROW + sg * 8) * 2,
                          d_iAS + (size_t)(b0 + r) * KS + half * KP + k0 + sg * 8);
                }
#pragma unroll
                for (int q = 0; q < 2; ++q) {
                    int idx = tid + 256 * q;
                    if (idx < 480) {
                        int r = idx >> 2, sg = idx & 3;
                        int s = r / JT, jt = r - s * JT;
                        cpa16(sa + (2 * A1_H + r * SROW + sg * 8) * 2,
                              d_WhhS + (size_t)(s * KP + j0 + jt) * KP + k0 + sg * 8);
                    }
                }
            };

            loadChunk(0, 0); CP_COMMIT();
            loadChunk(1, 1); CP_COMMIT();

#pragma unroll 1
            for (int ci = 0; ci < NCH; ++ci) {
                if (ci < NCH - 1) cp_wait<1>(); else cp_wait<0>();
                __syncthreads();
                if (ci + 2 < NCH) { loadChunk((ci + 2) % 3, ci + 2); CP_COMMIT(); }
                uint32_t stg = sbase + (ci % 3) * STG_GRU;
#pragma unroll
                for (int k16 = 0; k16 < 2; ++k16) {
                    uint32_t ko2 = (uint32_t)k16 * 32;
                    uint32_t ah[4], al[4];
                    ldsm4(ah, stg + aoffH + ko2);
                    ldsm4(al, stg + aoffL + ko2);
#pragma unroll
                    for (int q = 0; q < 7; ++q) {
                        uint32_t bb[4];
                        ldsm4(bb, stg + bfG[q] + ko2);
                        mma_f16(c[2 * q],     ah, bb[0], bb[1]);
                        mma_f16(c[2 * q],     al, bb[0], bb[1]);
                        mma_f16(c[2 * q + 1], ah, bb[2], bb[3]);
                        mma_f16(c[2 * q + 1], al, bb[2], bb[3]);
                    }
                    uint32_t b2[2];
                    ldsm2(b2, stg + bfG14 + ko2);
                    mma_f16(c[14], ah, b2[0], b2[1]);
                    mma_f16(c[14], al, b2[0], b2[1]);
                }
            }

#pragma unroll
            for (int hf = 0; hf < 2; ++hf) {
                int row = b0 + wid * 16 + g + hf * 8;
                int t = types[row * MAXN + vv], p = paths[row * MAXN + vv];
                const float* t1 = d_T1 + t * 3 * KP;
                const float* t2 = d_T2 + p * 3 * KP;
#pragma unroll
                for (int nf = 0; nf < 5; ++nf) {
                    int jb = j0 + nf * 8 + 2 * tig;
                    float h2[2];
#pragma unroll
                    for (int cl = 0; cl < 2; ++cl) {
                        int j = jb + cl;
                        int ci2 = hf * 2 + cl;
                        float h = 0.f;
                        if (j < HID) {
                            float hin = d_hin[(size_t)row * KP + j];
                            float rr = sigm(c[nf][ci2] + t1[j] + t2[j] + d_bhh3[j]);
                            float zz = sigm(c[nf + 5][ci2] + t1[KP + j] + t2[KP + j] +
                                            d_bhh3[KP + j]);
                            float nn = tanhf(t1[2 * KP + j] + t2[2 * KP + j] +
                                             rr * (c[nf + 10][ci2] + d_bhh3[2 * KP + j]));
                            h = (1.f - zz) * nn + zz * hin;
                        }
                        h2[cl] = h;
                    }
                    *(float2*)&d_hcur[(size_t)row * KP + jb] = make_float2(h2[0], h2[1]);
                    __half h0h, h0l, h1h, h1l;
                    hsplit(h2[0], h0h, h0l); hsplit(h2[1], h1h, h1l);
                    size_t o = (size_t)row * KS + jb;
                    *(__half2*)(d_hAS + o)      = __half2{h0h, h1h};
                    *(__half2*)(d_hAS + o + KP) = __half2{h0l, h1l};
                }
            }
        }
        if (v < 10) barx(bx, 2 + 2 * v);
    }
}

// ---------------- head pre: df scatter + tiny MLPs -> d_hcur[b][301..309) ---
__global__ void __launch_bounds__(256) k_headpre(
    const int* __restrict__ paths, const float* __restrict__ feats,
    const float* __restrict__ W_df1, const float* __restrict__ b_df1,
    const float* __restrict__ W_df2, const float* __restrict__ b_df2)
{
    __shared__ float sdf[8][28];
    __shared__ float s16[8][16];
    int lane = threadIdx.x & 31, w = threadIdx.x >> 5;
    int b = blockIdx.x * 8 + w;

    if (lane < 27) sdf[w][lane] = 0.f;
    __syncwarp();
    if (lane == 0) {
        for (int v = 0; v < MAXN; ++v) {
            int base = paths[b * MAXN + v] * 3;
            sdf[w][base]     = feats[(b * MAXN + v) * 3 + 0];
            sdf[w][base + 1] = feats[(b * MAXN + v) * 3 + 1];
            sdf[w][base + 2] = feats[(b * MAXN + v) * 3 + 2];
        }
    }
    __syncwarp();
    if (lane < 16) {
        float a = b_df1[lane];
        for (int k = 0; k < 27; ++k) a = fmaf(sdf[w][k], W_df1[lane * 27 + k], a);
        s16[w][lane] = fmaxf(a, 0.f);
    }
    __syncwarp();
    if (lane < 8) {
        float a = b_df2[lane];
        for (int k = 0; k < 16; ++k) a = fmaf(s16[w][k], W_df2[lane * 16 + k], a);
        d_hcur[(size_t)b * KP + HID + lane] = a;
    }
}

// ---------------- head GEMM: out[4096,112] = hcur[4096,320] @ Wfc^T + b -----
__global__ void __launch_bounds__(256) k_fc(float* __restrict__ out)
{
    __shared__ float4 sA[64][8];
    __shared__ float4 sW[64][9];
    int tid = threadIdx.x;
    int tx = tid & 31, ty = tid >> 5;
    int b0 = blockIdx.x * 64;
    int c0 = blockIdx.y * 64;

    float acc[8][2];
#pragma unroll
    for (int i = 0; i < 8; ++i) { acc[i][0] = 0.f; acc[i][1] = 0.f; }

    for (int k0 = 0; k0 < KP; k0 += 32) {
#pragma unroll
        for (int q = 0; q < 2; ++q) {
            int idx = tid + 256 * q;
            int r = idx >> 3, cc = idx & 7;
            sA[r][cc] = *(const float4*)&d_hcur[(size_t)(b0 + r) * KP + k0 + 4 * cc];
            sW[r][cc] = *(const float4*)&d_Wfc[(size_t)(c0 + r) * KP + k0 + 4 * cc];
        }
        __syncthreads();
#pragma unroll
        for (int kq = 0; kq < 8; ++kq) {
            float4 w0 = sW[tx][kq], w1 = sW[tx + 32][kq];
#pragma unroll
            for (int i = 0; i < 8; ++i) {
                float4 a = sA[ty + 8 * i][kq];
                acc[i][0] = fmaf(a.x, w0.x, acc[i][0]); acc[i][0] = fmaf(a.y, w0.y, acc[i][0]);
                acc[i][0] = fmaf(a.z, w0.z, acc[i][0]); acc[i][0] = fmaf(a.w, w0.w, acc[i][0]);
                acc[i][1] = fmaf(a.x, w1.x, acc[i][1]); acc[i][1] = fmaf(a.y, w1.y, acc[i][1]);
                acc[i][1] = fmaf(a.z, w1.z, acc[i][1]); acc[i][1] = fmaf(a.w, w1.w, acc[i][1]);
            }
        }
        __syncthreads();
    }

    int c1 = c0 + tx, c2 = c0 + tx + 32;
#pragma unroll
    for (int i = 0; i < 8; ++i) {
        int row = b0 + ty + 8 * i;
        if (c1 < 112) out[(size_t)row * 112 + c1] = acc[i][0] + d_bfc[c1];
        if (c2 < 112) out[(size_t)row * 112 + c2] = acc[i][1] + d_bfc[c2];
    }
}

// ---------------- launcher --------------------------------------------------
extern "C" void kernel_launch(void* const* d_in, const int* in_sizes, int n_in,
                              void* d_out, int out_size)
{
    const int*   types = (const int*)d_in[0];
    const int*   paths = (const int*)d_in[1];
    const int*   adj   = (const int*)d_in[2];
    const float* feats = (const float*)d_in[3];
    const float* W_ih  = (const float*)d_in[4];
    const float* W_hh  = (const float*)d_in[5];
    const float* b_ih  = (const float*)d_in[6];
    const float* b_hh  = (const float*)d_in[7];
    const float* Wg    = (const float*)d_in[8];
    const float* bg    = (const float*)d_in[9];
    const float* Wm    = (const float*)d_in[10];
    const float* W_df1 = (const float*)d_in[11];
    const float* b_df1 = (const float*)d_in[12];
    const float* W_df2 = (const float*)d_in[13];
    const float* b_df2 = (const float*)d_in[14];
    const float* W_fc1 = (const float*)d_in[15];
    const float* b_fc1 = (const float*)d_in[16];
    const float* W_fc2 = (const float*)d_in[17];
    const float* b_fc2 = (const float*)d_in[18];
    float* out = (float*)d_out;

    cudaFuncSetAttribute(k_main, cudaFuncAttributeMaxDynamicSharedMemorySize, SM_MAIN);

    const int tabN = NT * 3 * KP + PP * 3 * KP + 3 * KP + 2 * PP * KP;
    k_pad<<<(5 * HID * HID + 255) / 256, 256>>>(W_hh, Wg, Wm);
    k_tab<<<(tabN + 255) / 256, 256>>>(W_ih, b_ih, b_hh, Wg, bg, Wm);
    k_wfc<<<(112 * KP + 112 + 255) / 256, 256>>>(W_fc1, b_fc1, W_fc2, b_fc2);

    dim3 grid(32, 8);   // 256 blocks < 296 capacity -> all co-resident
    k_main<<<grid, 256, SM_MAIN>>>(types, paths, adj);

    k_headpre<<<BB / 8, 256>>>(paths, feats, W_df1, b_df1, W_df2, b_df2);
    dim3 gFC(BB / 64, 2);
    k_fc<<<gFC, 256>>>(out);
}

// round 16
// speedup vs baseline: 2.0263x; 1.0909x over previous
#include <cuda_runtime.h>
#include <cuda_fp16.h>
#include <cstdint>

#define BB 4096
#define MAXN 12
#define HID 301
#define NT 10
#define PP 9
#define VSTAT 310
#define KP 320          // padded hidden (= unique K)
#define KS 640          // activation storage: [hi(320) | lo(320)] fp16
#define JT 80           // j-cols per block -> grid 32 x 4 = 128 blocks (occ 1)
#define NJ 4            // j-blocks per batch tile
#define KC 32           // unique-K per chunk
#define NCH 10          // 320/32
#define SROW 40         // smem row stride in halves (80B)
#define THR 512

#define A1_H (128 * SROW)                       // 5120 halves (one A half-tile)
#define STG_GRU ((2 * A1_H + 240 * SROW) * 2)   // 39680 B
#define STG_GT  ((2 * A1_H + 160 * SROW) * 2)   // 33280 B
#define SM_MAIN (3 * STG_GRU)                   // 119040

// ---------------- scratch (device globals; zero-initialized) ----------------
__device__ __align__(16) float d_g[(size_t)BB * 11 * KP];
__device__ __align__(16) float d_hcur[(size_t)BB * KP];
__device__ __align__(16) float d_hin[(size_t)BB * KP];
__device__ __align__(16) __half d_hAS[(size_t)BB * KS];
__device__ __align__(16) __half d_iAS[(size_t)BB * KS];
__device__ __align__(16) __half d_WhhS[960 * KP];   // rows s*320+j
__device__ __align__(16) __half d_WgmS[640 * KP];   // rows m*320+j
__device__ unsigned d_bar[32 * 24];                 // monotonic phase counters
// epilogue tables (coalesced in j)
__device__ __align__(16) float d_T1[NT * 3 * KP];
__device__ __align__(16) float d_T2[PP * 3 * KP];
__device__ __align__(16) float d_bhh3[3 * KP];
__device__ __align__(16) float d_Tg[PP * KP];
__device__ __align__(16) float d_Tm[PP * KP];
// head GEMM weights
__device__ __align__(16) float d_Wfc[128 * KP];
__device__ __align__(16) float d_bfc[128];

__device__ __forceinline__ float sigm(float x) { return 1.f / (1.f + __expf(-x)); }
__device__ __forceinline__ void hsplit(float x, __half& hi, __half& lo) {
    hi = __float2half_rn(x);
    lo = __float2half_rn(x - __half2float(hi));
}
__device__ __forceinline__ void mma_f16(float c[4], const uint32_t a[4],
                                        uint32_t b0, uint32_t b1) {
    asm volatile(
        "mma.sync.aligned.m16n8k16.row.col.f32.f16.f16.f32 "
        "{%0,%1,%2,%3}, {%4,%5,%6,%7}, {%8,%9}, {%0,%1,%2,%3};"
        : "+f"(c[0]), "+f"(c[1]), "+f"(c[2]), "+f"(c[3])
        : "r"(a[0]), "r"(a[1]), "r"(a[2]), "r"(a[3]), "r"(b0), "r"(b1));
}
__device__ __forceinline__ void ldsm4(uint32_t* r, uint32_t addr) {
    asm volatile("ldmatrix.sync.aligned.m8n8.x4.shared.b16 {%0,%1,%2,%3}, [%4];"
                 : "=r"(r[0]), "=r"(r[1]), "=r"(r[2]), "=r"(r[3]) : "r"(addr));
}
__device__ __forceinline__ void ldsm2(uint32_t* r, uint32_t addr) {
    asm volatile("ldmatrix.sync.aligned.m8n8.x2.shared.b16 {%0,%1}, [%2];"
                 : "=r"(r[0]), "=r"(r[1]) : "r"(addr));
}
__device__ __forceinline__ void cpa16(uint32_t s, const void* g) {
    asm volatile("cp.async.ca.shared.global [%0], [%1], 16;" :: "r"(s), "l"(g));
}
#define CP_COMMIT() asm volatile("cp.async.commit_group;")
template<int N> __device__ __forceinline__ void cp_wait() {
    asm volatile("cp.async.wait_group %0;" :: "n"(N));
}

// per-batch-tile barrier among the NJ=4 j-blocks of bx. Monotonic counters.
__device__ __forceinline__ void barx(int bx, int k) {
    __syncthreads();
    if (threadIdx.x == 0) {
        __threadfence();
        unsigned* c = &d_bar[bx * 24 + k];
        unsigned old = atomicAdd(c, 1u);
        unsigned target = (old & ~3u) + 4u;
        while (atomicAdd(c, 0u) < target) { __nanosleep(64); }
        __threadfence();
    }
    __syncthreads();
}

// ---------------- weight repack (fp16, UNIQUE K) ----------------------------
__global__ void k_pad(const float* __restrict__ Whh, const float* __restrict__ Wg,
                      const float* __restrict__ Wm)
{
    int idx = blockIdx.x * blockDim.x + threadIdx.x;
    const int total = HID * HID;
    if (idx < 3 * total) {
        int s = idx / total, r = idx - s * total, j = r / HID, k = r - j * HID;
        d_WhhS[(size_t)(s * KP + j) * KP + k] = __float2half_rn(Whh[(s * HID + j) * HID + k]);
    } else if (idx < 5 * total) {
        int m = (idx - 3 * total) / total, r = (idx - 3 * total) % total;
        int j = r / HID, k = r - j * HID;
        const float* W = m ? Wm : Wg;
        d_WgmS[(size_t)(m * KP + j) * KP + k] = __float2half_rn(W[j * VSTAT + k]);
    }
}

// ---------------- epilogue table build --------------------------------------
__global__ void k_tab(const float* __restrict__ W_ih, const float* __restrict__ b_ih,
                      const float* __restrict__ b_hh,
                      const float* __restrict__ Wg, const float* __restrict__ bg,
                      const float* __restrict__ Wm)
{
    int idx = blockIdx.x * blockDim.x + threadIdx.x;
    const int TPK = 3 * KP;
    if (idx < NT * TPK) {
        int t = idx / TPK, r = idx - t * TPK, s = r / KP, j = r - s * KP;
        d_T1[idx] = (j < HID) ? W_ih[(size_t)(s * HID + j) * 19 + t] + b_ih[s * HID + j] : 0.f;
    } else if (idx < NT * TPK + PP * TPK) {
        int q = idx - NT * TPK;
        int p = q / TPK, r = q - p * TPK, s = r / KP, j = r - s * KP;
        d_T2[q] = (j < HID) ? W_ih[(size_t)(s * HID + j) * 19 + NT + p] : 0.f;
    } else if (idx < NT * TPK + PP * TPK + TPK) {
        int q = idx - NT * TPK - PP * TPK;
        int s = q / KP, j = q - s * KP;
        d_bhh3[q] = (j < HID) ? b_hh[s * HID + j] : 0.f;
    } else if (idx < NT * TPK + PP * TPK + TPK + PP * KP) {
        int q = idx - NT * TPK - PP * TPK - TPK;
        int p = q / KP, j = q - p * KP;
        d_Tg[q] = (j < HID) ? Wg[(size_t)j * VSTAT + HID + p] + bg[j] : 0.f;
    } else if (idx < NT * TPK + PP * TPK + TPK + 2 * PP * KP) {
        int q = idx - NT * TPK - PP * TPK - TPK - PP * KP;
        int p = q / KP, j = q - p * KP;
        d_Tm[q] = (j < HID) ? Wm[(size_t)j * VSTAT + HID + p] : 0.f;
    }
}

// ---------------- head weight pad build -------------------------------------
__global__ void k_wfc(const float* __restrict__ W_fc1, const float* __restrict__ b_fc1,
                      const float* __restrict__ W_fc2, const float* __restrict__ b_fc2)
{
    int idx = blockIdx.x * blockDim.x + threadIdx.x;
    if (idx < 112 * KP) {
        int o = idx / KP, k = idx - o * KP;
        float v = 0.f;
        if (k < HID + 8)
            v = (o < 56) ? W_fc1[o * (HID + 8) + k] : W_fc2[(o - 56) * (HID + 8) + k];
        d_Wfc[o * KP + k] = v;
    } else if (idx < 112 * KP + 112) {
        int o = idx - 112 * KP;
        d_bfc[o] = (o < 56) ? b_fc1[o] : b_fc2[o - 56];
    }
}

// ============================================================================
// Persistent recurrence kernel. Grid 32 x 4, 512 threads, occ 1.
// Warp layout 8M x 2N; warp tile: 16 rows x 40 j-cols x all gates.
// ============================================================================
__global__ void __launch_bounds__(THR, 1) k_main(
    const int* __restrict__ types, const int* __restrict__ paths,
    const int* __restrict__ adj)
{
    extern __shared__ __half sm[];
    int tid = threadIdx.x, lane = tid & 31, wid = tid >> 5;
    int g = lane >> 2, tig = lane & 3;
    int li = lane >> 3, lt = lane & 7;
    int wm = wid >> 1, wn = wid & 1;
    int bx = blockIdx.x, jy = blockIdx.y;
    int b0 = bx * 128, j0 = jy * JT;

    uint32_t sbase = (uint32_t)__cvta_generic_to_shared(sm);

    // fragment smem offsets
    uint32_t aoffH, aoffL, bfG[6], bfG2[3], bfT[4], bfT2[2];
    {
        int mrow = wm * 16 + (li & 1) * 8 + lt;
        aoffH = (uint32_t)(mrow * SROW + (li >> 1) * 8) * 2;
        aoffL = aoffH + A1_H * 2;
    }
#pragma unroll
    for (int s = 0; s < 3; ++s) {
#pragma unroll
        for (int part = 0; part < 2; ++part) {
            int nrow = s * JT + wn * 40 + part * 16 + (li >> 1) * 8 + lt;
            bfG[s * 2 + part] = (uint32_t)(2 * A1_H + nrow * SROW + (li & 1) * 8) * 2;
        }
        int nrow2 = s * JT + wn * 40 + 32 + lt;
        bfG2[s] = (uint32_t)(2 * A1_H + nrow2 * SROW + ((lane >> 3) & 1) * 8) * 2;
    }
#pragma unroll
    for (int s = 0; s < 2; ++s) {
#pragma unroll
        for (int part = 0; part < 2; ++part) {
            int nrow = s * JT + wn * 40 + part * 16 + (li >> 1) * 8 + lt;
            bfT[s * 2 + part] = (uint32_t)(2 * A1_H + nrow * SROW + (li & 1) * 8) * 2;
        }
        int nrow2 = s * JT + wn * 40 + 32 + lt;
        bfT2[s] = (uint32_t)(2 * A1_H + nrow2 * SROW + ((lane >> 3) & 1) * 8) * 2;
    }

    // ---------------- phase: h0 ----------------
    for (int idx = tid; idx < 128 * JT; idx += THR) {
        int r = idx / JT, jj = idx - r * JT;
        int j = j0 + jj;
        if (j >= HID) continue;
        int b = b0 + r;
        int t = types[b * MAXN], p = paths[b * MAXN];
        const float* t1 = d_T1 + t * 3 * KP;
        const float* t2 = d_T2 + p * 3 * KP;
        float rr = sigm(t1[j] + t2[j] + d_bhh3[j]);
        float zz = sigm(t1[KP + j] + t2[KP + j] + d_bhh3[KP + j]);
        float nn = tanhf(t1[2 * KP + j] + t2[2 * KP + j] + rr * d_bhh3[2 * KP + j]);
        float h = (1.f - zz) * nn;
        d_hcur[(size_t)b * KP + j] = h;
        __half hi, lo; hsplit(h, hi, lo);
        size_t o = (size_t)b * KS + j;
        d_hAS[o] = hi; d_hAS[o + KP] = lo;
    }
    barx(bx, 0);

    for (int v = 0; v < 11; ++v) {
        // ================= gate(v) phase =================
        {
            float* adjf = (float*)((char*)sm + 3 * STG_GT);   // [128][12]
            float c[10][4];
#pragma unroll
            for (int nf = 0; nf < 10; ++nf)
#pragma unroll
                for (int i = 0; i < 4; ++i) c[nf][i] = 0.f;

            auto loadChunk = [&](int st, int ci) {
                uint32_t sa = sbase + st * STG_GT;
                int k0 = ci * KC;
#pragma unroll
                for (int q = 0; q < 2; ++q) {           // A hi+lo: 1024 ops
                    int idx = tid + THR * q;
                    int half = idx >> 9;
                    int i2 = idx & 511;
                    int r = i2 >> 2, sg = i2 & 3;
                    cpa16(sa + (half * A1_H + r * SROW + sg * 8) * 2,
                          d_hAS + (size_t)(b0 + r) * KS + half * KP + k0 + sg * 8);
                }
#pragma unroll
                for (int q = 0; q < 2; ++q) {           // B: 160 rows x 4 = 640
                    int idx = tid + THR * q;
                    if (idx < 640) {
                        int r = idx >> 2, sg = idx & 3;
                        int s = r / JT, jt = r - s * JT;
                        cpa16(sa + (2 * A1_H + r * SROW + sg * 8) * 2,
                              d_WgmS + (size_t)(s * KP + j0 + jt) * KP + k0 + sg * 8);
                    }
                }
            };

            loadChunk(0, 0); CP_COMMIT();
            loadChunk(1, 1); CP_COMMIT();
            for (int idx = tid; idx < 128 * MAXN; idx += THR) {
                int r = idx / MAXN, u = idx - r * MAXN;
                adjf[idx] = (float)adj[(size_t)(b0 + r) * (MAXN * MAXN) + (v + 1) * MAXN + u];
            }

#pragma unroll 1
            for (int ci = 0; ci < NCH; ++ci) {
                if (ci < NCH - 1) cp_wait<1>(); else cp_wait<0>();
                __syncthreads();
                if (ci + 2 < NCH) { loadChunk((ci + 2) % 3, ci + 2); CP_COMMIT(); }
                uint32_t stg = sbase + (ci % 3) * STG_GT;
#pragma unroll
                for (int k16 = 0; k16 < 2; ++k16) {
                    uint32_t ko2 = (uint32_t)k16 * 32;
                    uint32_t ah[4], al[4];
                    ldsm4(ah, stg + aoffH + ko2);
                    ldsm4(al, stg + aoffL + ko2);
#pragma unroll
                    for (int s = 0; s < 2; ++s) {
                        uint32_t bb[4];
                        ldsm4(bb, stg + bfT[s * 2] + ko2);
                        mma_f16(c[s * 5 + 0], ah, bb[0], bb[1]);
                        mma_f16(c[s * 5 + 0], al, bb[0], bb[1]);
                        mma_f16(c[s * 5 + 1], ah, bb[2], bb[3]);
                        mma_f16(c[s * 5 + 1], al, bb[2], bb[3]);
                        ldsm4(bb, stg + bfT[s * 2 + 1] + ko2);
                        mma_f16(c[s * 5 + 2], ah, bb[0], bb[1]);
                        mma_f16(c[s * 5 + 2], al, bb[0], bb[1]);
                        mma_f16(c[s * 5 + 3], ah, bb[2], bb[3]);
                        mma_f16(c[s * 5 + 3], al, bb[2], bb[3]);
                        uint32_t b2[2];
                        ldsm2(b2, stg + bfT2[s] + ko2);
                        mma_f16(c[s * 5 + 4], ah, b2[0], b2[1]);
                        mma_f16(c[s * 5 + 4], al, b2[0], b2[1]);
                    }
                }
            }

            __syncthreads();
            float* g_s   = (float*)sm;             // [128][80]
            float* hin_s = (float*)sm + 128 * JT;  // [128][80]

            // ---- gate epilogue into smem (g/m pairs: c[nf], c[nf+5]) ----
#pragma unroll
            for (int hf = 0; hf < 2; ++hf) {
                int row = wm * 16 + g + hf * 8;
                int p = paths[(b0 + row) * MAXN + v];
                const float* tg = d_Tg + p * KP;
                const float* tm = d_Tm + p * KP;
#pragma unroll
                for (int nf = 0; nf < 5; ++nf) {
                    int jl = wn * 40 + nf * 8 + 2 * tig;
#pragma unroll
                    for (int cl = 0; cl < 2; ++cl) {
                        int j = j0 + jl + cl;
                        int ci2 = hf * 2 + cl;
                        float val = 0.f;
                        if (j < HID) {
                            float gv = sigm(c[nf][ci2] + tg[j]);
                            float mv = c[nf + 5][ci2] + tm[j];
                            val = gv * mv;
                        }
                        g_s[row * JT + jl + cl] = val;
                    }
                }
            }
            __syncthreads();

            for (int idx = tid; idx < 128 * JT; idx += THR) {
                int r = idx / JT, jj = idx - r * JT;
                float acc = 0.f;
                for (int u = 0; u < v; ++u) {
                    if (adjf[r * MAXN + u] != 0.f)
                        acc += d_g[((size_t)(b0 + r) * 11 + u) * KP + j0 + jj];
                }
                if (adjf[r * MAXN + v] != 0.f) acc += g_s[idx];
                hin_s[idx] = acc;
            }
            __syncthreads();

            for (int idx = tid; idx < 128 * (JT / 4); idx += THR) {
                int r = idx / (JT / 4), sg = idx - r * (JT / 4);
                float4 g4 = *(float4*)&g_s[r * JT + sg * 4];
                *(float4*)&d_g[((size_t)(b0 + r) * 11 + v) * KP + j0 + sg * 4] = g4;
                float4 h4 = *(float4*)&hin_s[r * JT + sg * 4];
                *(float4*)&d_hin[(size_t)(b0 + r) * KP + j0 + sg * 4] = h4;
                __half h0, l0, h1, l1, h2, l2, h3, l3;
                hsplit(h4.x, h0, l0); hsplit(h4.y, h1, l1);
                hsplit(h4.z, h2, l2); hsplit(h4.w, h3, l3);
                size_t o = (size_t)(b0 + r) * KS + j0 + sg * 4;
                __half2* ph_ = (__half2*)(d_iAS + o);
                ph_[0] = __half2{h0, h1}; ph_[1] = __half2{h2, h3};
                __half2* pl_ = (__half2*)(d_iAS + o + KP);
                pl_[0] = __half2{l0, l1}; pl_[1] = __half2{l2, l3};
            }
        }
        barx(bx, 1 + 2 * v);

        // ================= gru(v+1) phase =================
        {
            int vv = v + 1;
            float c[15][4];
#pragma unroll
            for (int nf = 0; nf < 15; ++nf)
#pragma unroll
                for (int i = 0; i < 4; ++i) c[nf][i] = 0.f;

            auto loadChunk = [&](int st, int ci) {
                uint32_t sa = sbase + st * STG_GRU;
                int k0 = ci * KC;
#pragma unroll
                for (int q = 0; q < 2; ++q) {           // A hi+lo
                    int idx = tid + THR * q;
                    int half = idx >> 9;
                    int i2 = idx & 511;
                    int r = i2 >> 2, sg = i2 & 3;
                    cpa16(sa + (half * A1_H + r * SROW + sg * 8) * 2,
                          d_iAS + (size_t)(b0 + r) * KS + half * KP + k0 + sg * 8);
                }
#pragma unroll
                for (int q = 0; q < 2; ++q) {           // B: 240 rows x 4 = 960
                    int idx = tid + THR * q;
                    if (idx < 960) {
                        int r = idx >> 2, sg = idx & 3;
                        int s = r / JT, jt = r - s * JT;
                        cpa16(sa + (2 * A1_H + r * SROW + sg * 8) * 2,
                              d_WhhS + (size_t)(s * KP + j0 + jt) * KP + k0 + sg * 8);
                    }
                }
            };

            loadChunk(0, 0); CP_COMMIT();
            loadChunk(1, 1); CP_COMMIT();

#pragma unroll 1
            for (int ci = 0; ci < NCH; ++ci) {
                if (ci < NCH - 1) cp_wait<1>(); else cp_wait<0>();
                __syncthreads();
                if (ci + 2 < NCH) { loadChunk((ci + 2) % 3, ci + 2); CP_COMMIT(); }
                uint32_t stg = sbase + (ci % 3) * STG_GRU;
#pragma unroll
                for (int k16 = 0; k16 < 2; ++k16) {
                    uint32_t ko2 = (uint32_t)k16 * 32;
                    uint32_t ah[4], al[4];
                    ldsm4(ah, stg + aoffH + ko2);
                    ldsm4(al, stg + aoffL + ko2);
#pragma unroll
                    for (int s = 0; s < 3; ++s) {
                        uint32_t bb[4];
                        ldsm4(bb, stg + bfG[s * 2] + ko2);
                        mma_f16(c[s * 5 + 0], ah, bb[0], bb[1]);
                        mma_f16(c[s * 5 + 0], al, bb[0], bb[1]);
                        mma_f16(c[s * 5 + 1], ah, bb[2], bb[3]);
                        mma_f16(c[s * 5 + 1], al, bb[2], bb[3]);
                        ldsm4(bb, stg + bfG[s * 2 + 1] + ko2);
                        mma_f16(c[s * 5 + 2], ah, bb[0], bb[1]);
                        mma_f16(c[s * 5 + 2], al, bb[0], bb[1]);
                        mma_f16(c[s * 5 + 3], ah, bb[2], bb[3]);
                        mma_f16(c[s * 5 + 3], al, bb[2], bb[3]);
                        uint32_t b2[2];
                        ldsm2(b2, stg + bfG2[s] + ko2);
                        mma_f16(c[s * 5 + 4], ah, b2[0], b2[1]);
                        mma_f16(c[s * 5 + 4], al, b2[0], b2[1]);
                    }
                }
            }

            // ---- fused GRU epilogue (register-resident r/z/n) ----
#pragma unroll
            for (int hf = 0; hf < 2; ++hf) {
                int row = b0 + wm * 16 + g + hf * 8;
                int t = types[row * MAXN + vv], p = paths[row * MAXN + vv];
                const float* t1 = d_T1 + t * 3 * KP;
                const float* t2 = d_T2 + p * 3 * KP;
#pragma unroll
                for (int nf = 0; nf < 5; ++nf) {
                    int jb = j0 + wn * 40 + nf * 8 + 2 * tig;
                    float h2[2];
#pragma unroll
                    for (int cl = 0; cl < 2; ++cl) {
                        int j = jb + cl;
                        int ci2 = hf * 2 + cl;
                        float h = 0.f;
                        if (j < HID) {
                            float hin = d_hin[(size_t)row * KP + j];
                            float rr = sigm(c[nf][ci2] + t1[j] + t2[j] + d_bhh3[j]);
                            float zz = sigm(c[nf + 5][ci2] + t1[KP + j] + t2[KP + j] +
                                            d_bhh3[KP + j]);
                            float nn = tanhf(t1[2 * KP + j] + t2[2 * KP + j] +
                                             rr * (c[nf + 10][ci2] + d_bhh3[2 * KP + j]));
                            h = (1.f - zz) * nn + zz * hin;
                        }
                        h2[cl] = h;
                    }
                    *(float2*)&d_hcur[(size_t)row * KP + jb] = make_float2(h2[0], h2[1]);
                    __half h0h, h0l, h1h, h1l;
                    hsplit(h2[0], h0h, h0l); hsplit(h2[1], h1h, h1l);
                    size_t o = (size_t)row * KS + jb;
                    *(__half2*)(d_hAS + o)      = __half2{h0h, h1h};
                    *(__half2*)(d_hAS + o + KP) = __half2{h0l, h1l};
                }
            }
        }
        if (v < 10) barx(bx, 2 + 2 * v);
    }
}

// ---------------- head pre: df scatter + tiny MLPs -> d_hcur[b][301..309) ---
__global__ void __launch_bounds__(256) k_headpre(
    const int* __restrict__ paths, const float* __restrict__ feats,
    const float* __restrict__ W_df1, const float* __restrict__ b_df1,
    const float* __restrict__ W_df2, const float* __restrict__ b_df2)
{
    __shared__ float sdf[8][28];
    __shared__ float s16[8][16];
    int lane = threadIdx.x & 31, w = threadIdx.x >> 5;
    int b = blockIdx.x * 8 + w;

    if (lane < 27) sdf[w][lane] = 0.f;
    __syncwarp();
    if (lane == 0) {
        for (int v = 0; v < MAXN; ++v) {
            int base = paths[b * MAXN + v] * 3;
            sdf[w][base]     = feats[(b * MAXN + v) * 3 + 0];
            sdf[w][base + 1] = feats[(b * MAXN + v) * 3 + 1];
            sdf[w][base + 2] = feats[(b * MAXN + v) * 3 + 2];
        }
    }
    __syncwarp();
    if (lane < 16) {
        float a = b_df1[lane];
        for (int k = 0; k < 27; ++k) a = fmaf(sdf[w][k], W_df1[lane * 27 + k], a);
        s16[w][lane] = fmaxf(a, 0.f);
    }
    __syncwarp();
    if (lane < 8) {
        float a = b_df2[lane];
        for (int k = 0; k < 16; ++k) a = fmaf(s16[w][k], W_df2[lane * 16 + k], a);
        d_hcur[(size_t)b * KP + HID + lane] = a;
    }
}

// ---------------- head GEMM: out[4096,112] = hcur[4096,320] @ Wfc^T + b -----
__global__ void __launch_bounds__(256) k_fc(float* __restrict__ out)
{
    __shared__ float4 sA[64][8];
    __shared__ float4 sW[64][9];
    int tid = threadIdx.x;
    int tx = tid & 31, ty = tid >> 5;
    int b0 = blockIdx.x * 64;
    int c0 = blockIdx.y * 64;

    float acc[8][2];
#pragma unroll
    for (int i = 0; i < 8; ++i) { acc[i][0] = 0.f; acc[i][1] = 0.f; }

    for (int k0 = 0; k0 < KP; k0 += 32) {
#pragma unroll
        for (int q = 0; q < 2; ++q) {
            int idx = tid + 256 * q;
            int r = idx >> 3, cc = idx & 7;
            sA[r][cc] = *(const float4*)&d_hcur[(size_t)(b0 + r) * KP + k0 + 4 * cc];
            sW[r][cc] = *(const float4*)&d_Wfc[(size_t)(c0 + r) * KP + k0 + 4 * cc];
        }
        __syncthreads();
#pragma unroll
        for (int kq = 0; kq < 8; ++kq) {
            float4 w0 = sW[tx][kq], w1 = sW[tx + 32][kq];
#pragma unroll
            for (int i = 0; i < 8; ++i) {
                float4 a = sA[ty + 8 * i][kq];
                acc[i][0] = fmaf(a.x, w0.x, acc[i][0]); acc[i][0] = fmaf(a.y, w0.y, acc[i][0]);
                acc[i][0] = fmaf(a.z, w0.z, acc[i][0]); acc[i][0] = fmaf(a.w, w0.w, acc[i][0]);
                acc[i][1] = fmaf(a.x, w1.x, acc[i][1]); acc[i][1] = fmaf(a.y, w1.y, acc[i][1]);
                acc[i][1] = fmaf(a.z, w1.z, acc[i][1]); acc[i][1] = fmaf(a.w, w1.w, acc[i][1]);
            }
        }
        __syncthreads();
    }

    int c1 = c0 + tx, c2 = c0 + tx + 32;
#pragma unroll
    for (int i = 0; i < 8; ++i) {
        int row = b0 + ty + 8 * i;
        if (c1 < 112) out[(size_t)row * 112 + c1] = acc[i][0] + d_bfc[c1];
        if (c2 < 112) out[(size_t)row * 112 + c2] = acc[i][1] + d_bfc[c2];
    }
}

// ---------------- launcher --------------------------------------------------
extern "C" void kernel_launch(void* const* d_in, const int* in_sizes, int n_in,
                              void* d_out, int out_size)
{
    const int*   types = (const int*)d_in[0];
    const int*   paths = (const int*)d_in[1];
    const int*   adj   = (const int*)d_in[2];
    const float* feats = (const float*)d_in[3];
    const float* W_ih  = (const float*)d_in[4];
    const float* W_hh  = (const float*)d_in[5];
    const float* b_ih  = (const float*)d_in[6];
    const float* b_hh  = (const float*)d_in[7];
    const float* Wg    = (const float*)d_in[8];
    const float* bg    = (const float*)d_in[9];
    const float* Wm    = (const float*)d_in[10];
    const float* W_df1 = (const float*)d_in[11];
    const float* b_df1 = (const float*)d_in[12];
    const float* W_df2 = (const float*)d_in[13];
    const float* b_df2 = (const float*)d_in[14];
    const float* W_fc1 = (const float*)d_in[15];
    const float* b_fc1 = (const float*)d_in[16];
    const float* W_fc2 = (const float*)d_in[17];
    const float* b_fc2 = (const float*)d_in[18];
    float* out = (float*)d_out;

    cudaFuncSetAttribute(k_main, cudaFuncAttributeMaxDynamicSharedMemorySize, SM_MAIN);

    const int tabN = NT * 3 * KP + PP * 3 * KP + 3 * KP + 2 * PP * KP;
    k_pad<<<(5 * HID * HID + 255) / 256, 256>>>(W_hh, Wg, Wm);
    k_tab<<<(tabN + 255) / 256, 256>>>(W_ih, b_ih, b_hh, Wg, bg, Wm);
    k_wfc<<<(112 * KP + 112 + 255) / 256, 256>>>(W_fc1, b_fc1, W_fc2, b_fc2);

    dim3 grid(32, NJ);   // 128 blocks, occ 1 -> all co-resident
    k_main<<<grid, THR, SM_MAIN>>>(types, paths, adj);

    k_headpre<<<BB / 8, 256>>>(paths, feats, W_df1, b_df1, W_df2, b_df2);
    dim3 gFC(BB / 64, 2);
    k_fc<<<gFC, 256>>>(out);
}